// round 2
// baseline (speedup 1.0000x reference)
#include <cuda_runtime.h>
#include <cuda_bf16.h>
#include <math.h>

#define NN 50000
#define EE 800000
#define ET (EE + NN)      // edges + self loops = 850000
#define C0 256            // heads*hid = 4*64
#define H0 4
#define HD 64
#define C1 32
#define NEG 0.2f

// ---------------- device scratch (static: allowed) ----------------
__device__ float g_h0[NN * C0];      // h0 = x@W0, later reused as BN+ReLU output
__device__ float g_out0[NN * C0];    // layer0 aggregation output
__device__ float g_as0[NN * H0];
__device__ float g_ad0[NN * H0];
__device__ float g_m0[NN * H0];
__device__ float g_den0[NN * H0];
__device__ float g_w0[ET * H0];      // per-edge exp weights, layer0
__device__ float g_h1[NN * C1];
__device__ float g_as1[NN];
__device__ float g_ad1[NN];
__device__ float g_m1[NN];
__device__ float g_den1[NN];
__device__ float g_w1[ET];
__device__ float g_gsum[C1];

// ---------------- helpers ----------------
__device__ __forceinline__ void atomicMaxF(float* addr, float v) {
    // sign-split trick: correct for all float orderings (incl. -inf init)
    if (v >= 0.0f) {
        atomicMax((int*)addr, __float_as_int(v));
    } else {
        atomicMin((unsigned int*)addr, __float_as_uint(v));
    }
}

// edge_index is int32 (JAX default x64-disabled downcasts int64 -> int32)
__device__ __forceinline__ void edge_sd(const int* ei, int e, int& s, int& d) {
    if (e < EE) { s = ei[e]; d = ei[EE + e]; }
    else        { s = e - EE; d = e - EE; }
}

// ---------------- init ----------------
__global__ void init_kernel(float* emb) {
    int i = blockIdx.x * blockDim.x + threadIdx.x;
    int stride = gridDim.x * blockDim.x;
    for (int j = i; j < NN * C0; j += stride) g_out0[j] = 0.0f;
    for (int j = i; j < NN * C1; j += stride) emb[j] = 0.0f;
    for (int j = i; j < NN * H0; j += stride) { g_m0[j] = -INFINITY; g_den0[j] = 0.0f; }
    for (int j = i; j < NN; j += stride)      { g_m1[j] = -INFINITY; g_den1[j] = 0.0f; }
    if (i < C1) g_gsum[i] = 0.0f;
}

// ---------------- generic tiled SIMT GEMM: C[M,Ncol] = A[M,K] @ B[K,Ncol] ----------------
// BM=64, BN=64, BK=16, 256 threads, 4x4 per thread
__device__ __forceinline__ void gemm_body(const float* __restrict__ A,
                                          const float* __restrict__ B,
                                          float* __restrict__ C,
                                          int M, int K, int Ncol) {
    __shared__ float sA[16][64];
    __shared__ float sB[16][64 + 4];
    int tid = threadIdx.x;
    int brow = blockIdx.y * 64, bcol = blockIdx.x * 64;
    float acc[4][4] = {};
    int tr = (tid / 16) * 4, tc = (tid % 16) * 4;

    for (int k0 = 0; k0 < K; k0 += 16) {
        #pragma unroll
        for (int i = tid; i < 64 * 16; i += 256) {
            int r = i >> 4, c = i & 15;
            int gr = brow + r, gc = k0 + c;
            sA[c][r] = (gr < M) ? A[gr * K + gc] : 0.0f;   // K is a multiple of 16 here
        }
        #pragma unroll
        for (int i = tid; i < 16 * 64; i += 256) {
            int r = i >> 6, c = i & 63;
            int gr = k0 + r, gc = bcol + c;
            sB[r][c] = (gc < Ncol) ? B[gr * Ncol + gc] : 0.0f;
        }
        __syncthreads();
        #pragma unroll
        for (int kk = 0; kk < 16; kk++) {
            float a0 = sA[kk][tr], a1 = sA[kk][tr + 1], a2 = sA[kk][tr + 2], a3 = sA[kk][tr + 3];
            float b0 = sB[kk][tc], b1 = sB[kk][tc + 1], b2 = sB[kk][tc + 2], b3 = sB[kk][tc + 3];
            acc[0][0] += a0 * b0; acc[0][1] += a0 * b1; acc[0][2] += a0 * b2; acc[0][3] += a0 * b3;
            acc[1][0] += a1 * b0; acc[1][1] += a1 * b1; acc[1][2] += a1 * b2; acc[1][3] += a1 * b3;
            acc[2][0] += a2 * b0; acc[2][1] += a2 * b1; acc[2][2] += a2 * b2; acc[2][3] += a2 * b3;
            acc[3][0] += a3 * b0; acc[3][1] += a3 * b1; acc[3][2] += a3 * b2; acc[3][3] += a3 * b3;
        }
        __syncthreads();
    }
    #pragma unroll
    for (int r = 0; r < 4; r++) {
        int gr = brow + tr + r;
        if (gr >= M) continue;
        #pragma unroll
        for (int c = 0; c < 4; c++) {
            int gc = bcol + tc + c;
            if (gc < Ncol) C[gr * Ncol + gc] = acc[r][c];
        }
    }
}

__global__ void gemm0_kernel(const float* __restrict__ A, const float* __restrict__ B) {
    gemm_body(A, B, g_h0, NN, 128, C0);
}
__global__ void gemm1_kernel(const float* __restrict__ B) {
    gemm_body(g_h0, B, g_h1, NN, C0, C1);
}

// ---------------- alpha (layer 0): warp per (node, head) ----------------
__global__ void alpha0_kernel(const float* __restrict__ a_src, const float* __restrict__ a_dst) {
    int w = blockIdx.x * (blockDim.x >> 5) + (threadIdx.x >> 5);
    if (w >= NN * H0) return;
    int lane = threadIdx.x & 31;
    int n = w >> 2, h = w & 3;
    const float* row = g_h0 + n * C0 + h * HD;
    float v0 = row[lane], v1 = row[lane + 32];
    float as = v0 * a_src[h * HD + lane] + v1 * a_src[h * HD + lane + 32];
    float ad = v0 * a_dst[h * HD + lane] + v1 * a_dst[h * HD + lane + 32];
    #pragma unroll
    for (int off = 16; off; off >>= 1) {
        as += __shfl_down_sync(0xffffffffu, as, off);
        ad += __shfl_down_sync(0xffffffffu, ad, off);
    }
    if (lane == 0) { g_as0[w] = as; g_ad0[w] = ad; }
}

// ---------------- layer0 attention passes ----------------
__global__ void edge_max0(const int* __restrict__ ei) {
    int e = blockIdx.x * blockDim.x + threadIdx.x;
    if (e >= ET) return;
    int s, d; edge_sd(ei, e, s, d);
    #pragma unroll
    for (int h = 0; h < H0; h++) {
        float v = g_as0[s * H0 + h] + g_ad0[d * H0 + h];
        v = (v > 0.0f) ? v : NEG * v;
        atomicMaxF(&g_m0[d * H0 + h], v);
    }
}

__global__ void edge_exp0(const int* __restrict__ ei) {
    int e = blockIdx.x * blockDim.x + threadIdx.x;
    if (e >= ET) return;
    int s, d; edge_sd(ei, e, s, d);
    #pragma unroll
    for (int h = 0; h < H0; h++) {
        float v = g_as0[s * H0 + h] + g_ad0[d * H0 + h];
        v = (v > 0.0f) ? v : NEG * v;
        float w = __expf(v - g_m0[d * H0 + h]);
        g_w0[e * H0 + h] = w;
        atomicAdd(&g_den0[d * H0 + h], w);
    }
}

// warp per edge, 256 atomic adds
__global__ void agg0_kernel(const int* __restrict__ ei) {
    int e = blockIdx.x * (blockDim.x >> 5) + (threadIdx.x >> 5);
    if (e >= ET) return;
    int lane = threadIdx.x & 31;
    int s, d; edge_sd(ei, e, s, d);
    float coef[H0];
    #pragma unroll
    for (int h = 0; h < H0; h++) coef[h] = g_w0[e * H0 + h] / g_den0[d * H0 + h];
    const float* hrow = g_h0 + s * C0;
    float* orow = g_out0 + d * C0;
    #pragma unroll
    for (int j = 0; j < 8; j++) {
        int c = lane + j * 32;
        atomicAdd(&orow[c], hrow[c] * coef[c >> 6]);
    }
}

// ---------------- bias + BN(eval) + ReLU; out0 -> h0 (reuse) ----------------
__global__ void bnrelu_kernel(const float* __restrict__ b0,
                              const float* __restrict__ gamma, const float* __restrict__ beta,
                              const float* __restrict__ mean, const float* __restrict__ var) {
    int i = blockIdx.x * blockDim.x + threadIdx.x;
    if (i >= NN * C0) return;
    int c = i & (C0 - 1);
    float v = g_out0[i] + b0[c];
    v = (v - mean[c]) * (gamma[c] * rsqrtf(var[c] + 1e-5f)) + beta[c];
    g_h0[i] = fmaxf(v, 0.0f);
}

// ---------------- alpha (layer 1): warp per node ----------------
__global__ void alpha1_kernel(const float* __restrict__ a_src, const float* __restrict__ a_dst) {
    int n = blockIdx.x * (blockDim.x >> 5) + (threadIdx.x >> 5);
    if (n >= NN) return;
    int lane = threadIdx.x & 31;
    float v = g_h1[n * C1 + lane];
    float as = v * a_src[lane];
    float ad = v * a_dst[lane];
    #pragma unroll
    for (int off = 16; off; off >>= 1) {
        as += __shfl_down_sync(0xffffffffu, as, off);
        ad += __shfl_down_sync(0xffffffffu, ad, off);
    }
    if (lane == 0) { g_as1[n] = as; g_ad1[n] = ad; }
}

__global__ void edge_max1(const int* __restrict__ ei) {
    int e = blockIdx.x * blockDim.x + threadIdx.x;
    if (e >= ET) return;
    int s, d; edge_sd(ei, e, s, d);
    float v = g_as1[s] + g_ad1[d];
    v = (v > 0.0f) ? v : NEG * v;
    atomicMaxF(&g_m1[d], v);
}

__global__ void edge_exp1(const int* __restrict__ ei) {
    int e = blockIdx.x * blockDim.x + threadIdx.x;
    if (e >= ET) return;
    int s, d; edge_sd(ei, e, s, d);
    float v = g_as1[s] + g_ad1[d];
    v = (v > 0.0f) ? v : NEG * v;
    float w = __expf(v - g_m1[d]);
    g_w1[e] = w;
    atomicAdd(&g_den1[d], w);
}

// warp per edge, 32 cols
__global__ void agg1_kernel(const int* __restrict__ ei, float* __restrict__ emb) {
    int e = blockIdx.x * (blockDim.x >> 5) + (threadIdx.x >> 5);
    if (e >= ET) return;
    int lane = threadIdx.x & 31;
    int s, d; edge_sd(ei, e, s, d);
    float coef = g_w1[e] / g_den1[d];
    atomicAdd(&emb[d * C1 + lane], g_h1[s * C1 + lane] * coef);
}

// ---------------- add bias b1, accumulate column sums for graph embedding ----------------
__global__ void finalize1_kernel(float* __restrict__ emb, const float* __restrict__ b1) {
    int tid = blockIdx.x * blockDim.x + threadIdx.x;
    int c = tid & 31;
    int nlanes = (gridDim.x * blockDim.x) >> 5;
    int n0 = tid >> 5;
    float bias = b1[c];
    float local = 0.0f;
    for (int n = n0; n < NN; n += nlanes) {
        float v = emb[n * C1 + c] + bias;
        emb[n * C1 + c] = v;
        local += v;
    }
    atomicAdd(&g_gsum[c], local);
}

// ---------------- prediction head (1 block, 64 threads) ----------------
__global__ void predict_kernel(const float* __restrict__ hW1, const float* __restrict__ hb1,
                               const float* __restrict__ hW2, const float* __restrict__ hb2,
                               float* __restrict__ out, int pred_idx) {
    __shared__ float ge[C1];
    __shared__ float red[64];
    int t = threadIdx.x;
    if (t < C1) ge[t] = g_gsum[t] * (1.0f / (float)NN);
    __syncthreads();
    float s = hb1[t];
    #pragma unroll
    for (int c = 0; c < C1; c++) s += ge[c] * hW1[c * 64 + t];
    float v = fmaxf(s, 0.0f) * hW2[t];
    red[t] = v;
    __syncthreads();
    #pragma unroll
    for (int off = 32; off > 0; off >>= 1) {
        if (t < off) red[t] += red[t + off];
        __syncthreads();
    }
    if (t == 0) out[pred_idx] = red[0] + hb2[0];
}

// ---------------- launch ----------------
extern "C" void kernel_launch(void* const* d_in, const int* in_sizes, int n_in,
                              void* d_out, int out_size) {
    const float* x       = (const float*)d_in[0];
    const int*   ei      = (const int*)d_in[1];
    const float* W0      = (const float*)d_in[2];
    const float* a_src0  = (const float*)d_in[3];
    const float* a_dst0  = (const float*)d_in[4];
    const float* b0      = (const float*)d_in[5];
    const float* bn_g    = (const float*)d_in[6];
    const float* bn_b    = (const float*)d_in[7];
    const float* bn_m    = (const float*)d_in[8];
    const float* bn_v    = (const float*)d_in[9];
    const float* W1      = (const float*)d_in[10];
    const float* a_src1  = (const float*)d_in[11];
    const float* a_dst1  = (const float*)d_in[12];
    const float* b1      = (const float*)d_in[13];
    const float* hW1     = (const float*)d_in[14];
    const float* hb1     = (const float*)d_in[15];
    const float* hW2     = (const float*)d_in[16];
    const float* hb2     = (const float*)d_in[17];
    float* out = (float*)d_out;

    // init scratch + output
    init_kernel<<<1024, 256>>>(out);

    // layer 0
    {
        dim3 grid(C0 / 64, (NN + 63) / 64);
        gemm0_kernel<<<grid, 256>>>(x, W0);
    }
    alpha0_kernel<<<(NN * H0 * 32 + 255) / 256, 256>>>(a_src0, a_dst0);
    edge_max0<<<(ET + 255) / 256, 256>>>(ei);
    edge_exp0<<<(ET + 255) / 256, 256>>>(ei);
    agg0_kernel<<<(ET * 32 + 255) / 256, 256>>>(ei);
    bnrelu_kernel<<<(NN * C0 + 255) / 256, 256>>>(b0, bn_g, bn_b, bn_m, bn_v);

    // layer 1
    {
        dim3 grid(1, (NN + 63) / 64);
        gemm1_kernel<<<grid, 256>>>(W1);
    }
    alpha1_kernel<<<(NN * 32 + 255) / 256, 256>>>(a_src1, a_dst1);
    edge_max1<<<(ET + 255) / 256, 256>>>(ei);
    edge_exp1<<<(ET + 255) / 256, 256>>>(ei);
    agg1_kernel<<<(ET * 32 + 255) / 256, 256>>>(ei, out);
    finalize1_kernel<<<256, 256>>>(out, b1);
    predict_kernel<<<1, 64>>>(hW1, hb1, hW2, hb2, out, out_size - 1);
}

// round 3
// speedup vs baseline: 1.4325x; 1.4325x over previous
#include <cuda_runtime.h>
#include <cuda_bf16.h>
#include <math.h>

#define NN 50000
#define EE 800000
#define ET (EE + NN)      // edges + self loops
#define C0 256            // heads*hid = 4*64
#define H0 4
#define HD 64
#define C1 32
#define NEG 0.2f

// ---------------- device scratch ----------------
__device__ float g_h0[NN * C0];      // h0 = x@W0
__device__ float g_hb[NN * C0];      // layer0 output after agg+BN+ReLU
__device__ float g_as0[NN * H0];
__device__ float g_ad0[NN * H0];
__device__ float g_h1[NN * C1];
__device__ float g_as1[NN];
__device__ float g_ad1[NN];
__device__ float g_gsum[C1];
// CSR by destination
__device__ int g_cnt[NN];
__device__ int g_ptr[NN + 1];
__device__ int g_cur[NN];
__device__ int g_csr_src[ET];

// ---------------- init: cnt=1 (self loops), gsum=0 ----------------
__global__ void init_kernel() {
    int i = blockIdx.x * blockDim.x + threadIdx.x;
    int stride = gridDim.x * blockDim.x;
    for (int j = i; j < NN; j += stride) g_cnt[j] = 1;
    if (i < C1) g_gsum[i] = 0.0f;
}

// ---------------- histogram of dst over the EE real edges ----------------
__global__ void hist_kernel(const int* __restrict__ ei) {
    int e = blockIdx.x * blockDim.x + threadIdx.x;
    if (e >= EE) return;
    atomicAdd(&g_cnt[ei[EE + e]], 1);
}

// ---------------- single-block exclusive scan over 50K counts ----------------
__global__ void scan_kernel() {
    __shared__ int sums[1024];
    int t = threadIdx.x;
    const int CH = (NN + 1023) / 1024;   // 49
    int base = t * CH;
    int local = 0;
    for (int i = 0; i < CH; i++) {
        int idx = base + i;
        if (idx < NN) local += g_cnt[idx];
    }
    sums[t] = local;
    __syncthreads();
    // Hillis-Steele inclusive scan
    for (int off = 1; off < 1024; off <<= 1) {
        int v = (t >= off) ? sums[t - off] : 0;
        __syncthreads();
        sums[t] += v;
        __syncthreads();
    }
    int run = sums[t] - local;   // exclusive prefix
    for (int i = 0; i < CH; i++) {
        int idx = base + i;
        if (idx < NN) {
            g_ptr[idx] = run;
            g_cur[idx] = run;
            run += g_cnt[idx];
        }
    }
    if (t == 1023) g_ptr[NN] = run;   // == ET
}

// ---------------- scatter edges (incl. self loops) into CSR ----------------
__global__ void scatter_kernel(const int* __restrict__ ei) {
    int e = blockIdx.x * blockDim.x + threadIdx.x;
    if (e >= ET) return;
    int s, d;
    if (e < EE) { s = ei[e]; d = ei[EE + e]; }
    else        { s = e - EE; d = s; }
    int pos = atomicAdd(&g_cur[d], 1);
    g_csr_src[pos] = s;
}

// ---------------- tiled SIMT GEMM tile: writes C, leaves acc for epilogue ----------------
// BM=64, BN=64, BK=16, 256 threads, 4x4 per thread
__device__ __forceinline__ void gemm_tile(const float* __restrict__ A,
                                          const float* __restrict__ B,
                                          float* __restrict__ C,
                                          int M, int K, int Ncol,
                                          float acc[4][4]) {
    __shared__ float sA[16][64];
    __shared__ float sB[16][64 + 4];
    int tid = threadIdx.x;
    int brow = blockIdx.y * 64, bcol = blockIdx.x * 64;
    int tr = (tid / 16) * 4, tc = (tid % 16) * 4;
    #pragma unroll
    for (int r = 0; r < 4; r++)
        #pragma unroll
        for (int c = 0; c < 4; c++) acc[r][c] = 0.0f;

    for (int k0 = 0; k0 < K; k0 += 16) {
        #pragma unroll
        for (int i = tid; i < 64 * 16; i += 256) {
            int r = i >> 4, c = i & 15;
            int gr = brow + r, gc = k0 + c;
            sA[c][r] = (gr < M) ? A[gr * K + gc] : 0.0f;
        }
        #pragma unroll
        for (int i = tid; i < 16 * 64; i += 256) {
            int r = i >> 6, c = i & 63;
            int gr = k0 + r, gc = bcol + c;
            sB[r][c] = (gc < Ncol) ? B[gr * Ncol + gc] : 0.0f;
        }
        __syncthreads();
        #pragma unroll
        for (int kk = 0; kk < 16; kk++) {
            float a0 = sA[kk][tr], a1 = sA[kk][tr + 1], a2 = sA[kk][tr + 2], a3 = sA[kk][tr + 3];
            float b0 = sB[kk][tc], b1 = sB[kk][tc + 1], b2 = sB[kk][tc + 2], b3 = sB[kk][tc + 3];
            acc[0][0] += a0 * b0; acc[0][1] += a0 * b1; acc[0][2] += a0 * b2; acc[0][3] += a0 * b3;
            acc[1][0] += a1 * b0; acc[1][1] += a1 * b1; acc[1][2] += a1 * b2; acc[1][3] += a1 * b3;
            acc[2][0] += a2 * b0; acc[2][1] += a2 * b1; acc[2][2] += a2 * b2; acc[2][3] += a2 * b3;
            acc[3][0] += a3 * b0; acc[3][1] += a3 * b1; acc[3][2] += a3 * b2; acc[3][3] += a3 * b3;
        }
        __syncthreads();
    }
    #pragma unroll
    for (int r = 0; r < 4; r++) {
        int gr = brow + tr + r;
        if (gr >= M) continue;
        #pragma unroll
        for (int c = 0; c < 4; c++) {
            int gc = bcol + tc + c;
            if (gc < Ncol) C[gr * Ncol + gc] = acc[r][c];
        }
    }
}

// gemm0 + fused alpha0: block col == one head (64 cols)
__global__ void gemm0_kernel(const float* __restrict__ A, const float* __restrict__ B,
                             const float* __restrict__ a_src, const float* __restrict__ a_dst) {
    float acc[4][4];
    gemm_tile(A, B, g_h0, NN, 128, C0, acc);

    int tid = threadIdx.x;
    int head = blockIdx.x;              // bcol/64
    int brow = blockIdx.y * 64;
    int tr = (tid / 16) * 4, tc = (tid % 16) * 4;
    float as_p[4] = {0, 0, 0, 0}, ad_p[4] = {0, 0, 0, 0};
    #pragma unroll
    for (int c = 0; c < 4; c++) {
        float av = a_src[head * HD + tc + c];
        float dv = a_dst[head * HD + tc + c];
        #pragma unroll
        for (int r = 0; r < 4; r++) {
            as_p[r] += acc[r][c] * av;
            ad_p[r] += acc[r][c] * dv;
        }
    }
    #pragma unroll
    for (int off = 8; off >= 1; off >>= 1) {
        #pragma unroll
        for (int r = 0; r < 4; r++) {
            as_p[r] += __shfl_down_sync(0xffffffffu, as_p[r], off, 16);
            ad_p[r] += __shfl_down_sync(0xffffffffu, ad_p[r], off, 16);
        }
    }
    if ((tid & 15) == 0) {
        #pragma unroll
        for (int r = 0; r < 4; r++) {
            int gr = brow + tr + r;
            if (gr < NN) {
                g_as0[gr * H0 + head] = as_p[r];
                g_ad0[gr * H0 + head] = ad_p[r];
            }
        }
    }
}

// gemm1 + fused alpha1 (1 head, 32 valid cols out of the 64-wide tile)
__global__ void gemm1_kernel(const float* __restrict__ B,
                             const float* __restrict__ a_src, const float* __restrict__ a_dst) {
    float acc[4][4];
    gemm_tile(g_hb, B, g_h1, NN, C0, C1, acc);

    int tid = threadIdx.x;
    int brow = blockIdx.y * 64;
    int tr = (tid / 16) * 4, tc = (tid % 16) * 4;
    float as_p[4] = {0, 0, 0, 0}, ad_p[4] = {0, 0, 0, 0};
    #pragma unroll
    for (int c = 0; c < 4; c++) {
        int col = tc + c;
        float av = (col < C1) ? a_src[col] : 0.0f;
        float dv = (col < C1) ? a_dst[col] : 0.0f;
        #pragma unroll
        for (int r = 0; r < 4; r++) {
            as_p[r] += acc[r][c] * av;
            ad_p[r] += acc[r][c] * dv;
        }
    }
    #pragma unroll
    for (int off = 8; off >= 1; off >>= 1) {
        #pragma unroll
        for (int r = 0; r < 4; r++) {
            as_p[r] += __shfl_down_sync(0xffffffffu, as_p[r], off, 16);
            ad_p[r] += __shfl_down_sync(0xffffffffu, ad_p[r], off, 16);
        }
    }
    if ((tid & 15) == 0) {
        #pragma unroll
        for (int r = 0; r < 4; r++) {
            int gr = brow + tr + r;
            if (gr < NN) {
                g_as1[gr] = as_p[r];
                g_ad1[gr] = ad_p[r];
            }
        }
    }
}

__device__ __forceinline__ float leaky(float v) { return (v > 0.0f) ? v : NEG * v; }

// ---------------- layer0: CSR softmax + aggregate + bias + BN + ReLU, warp per node ----------------
__global__ void agg0_csr(const float* __restrict__ b0,
                         const float* __restrict__ bn_g, const float* __restrict__ bn_b,
                         const float* __restrict__ bn_m, const float* __restrict__ bn_v) {
    int w = (blockIdx.x * blockDim.x + threadIdx.x) >> 5;
    if (w >= NN) return;
    int lane = threadIdx.x & 31;
    int n = w;
    int beg = g_ptr[n], end = g_ptr[n + 1];

    float4 adn = *(const float4*)(g_ad0 + n * H0);
    float ad0 = adn.x, ad1 = adn.y, ad2 = adn.z, ad3 = adn.w;

    // phase 1: per-head max over incoming edges (lanes over edges)
    float m0 = -INFINITY, m1 = -INFINITY, m2 = -INFINITY, m3 = -INFINITY;
    for (int i = beg + lane; i < end; i += 32) {
        int s = g_csr_src[i];
        float4 av = *(const float4*)(g_as0 + s * H0);
        m0 = fmaxf(m0, leaky(av.x + ad0));
        m1 = fmaxf(m1, leaky(av.y + ad1));
        m2 = fmaxf(m2, leaky(av.z + ad2));
        m3 = fmaxf(m3, leaky(av.w + ad3));
    }
    #pragma unroll
    for (int off = 16; off >= 1; off >>= 1) {
        m0 = fmaxf(m0, __shfl_xor_sync(0xffffffffu, m0, off));
        m1 = fmaxf(m1, __shfl_xor_sync(0xffffffffu, m1, off));
        m2 = fmaxf(m2, __shfl_xor_sync(0xffffffffu, m2, off));
        m3 = fmaxf(m3, __shfl_xor_sync(0xffffffffu, m3, off));
    }

    // phase 2: serial over edges; lanes over columns (float4 x2 per lane)
    float s0 = 0, s1 = 0, s2 = 0, s3 = 0;
    float4 accA = {0, 0, 0, 0}, accB = {0, 0, 0, 0};
    int hA = lane >> 4;          // head of cols 4*lane..4*lane+3  (0 or 1)
    for (int i = beg; i < end; i++) {
        int s = g_csr_src[i];
        float4 av = *(const float4*)(g_as0 + s * H0);
        float w0 = __expf(leaky(av.x + ad0) - m0);
        float w1 = __expf(leaky(av.y + ad1) - m1);
        float w2 = __expf(leaky(av.z + ad2) - m2);
        float w3 = __expf(leaky(av.w + ad3) - m3);
        s0 += w0; s1 += w1; s2 += w2; s3 += w3;
        const float4* hr = (const float4*)(g_h0 + s * C0);
        float4 v0 = hr[lane];
        float4 v1 = hr[32 + lane];
        float wa = hA ? w1 : w0;        // head 0/1
        float wb = hA ? w3 : w2;        // head 2/3
        accA.x += v0.x * wa; accA.y += v0.y * wa; accA.z += v0.z * wa; accA.w += v0.w * wa;
        accB.x += v1.x * wb; accB.y += v1.y * wb; accB.z += v1.z * wb; accB.w += v1.w * wb;
    }
    float invA = 1.0f / (hA ? s1 : s0);
    float invB = 1.0f / (hA ? s3 : s2);

    // epilogue: +b0, BN(eval), ReLU
    int cA = 4 * lane, cB = 128 + 4 * lane;
    float4 bA = *(const float4*)(b0 + cA),   bB = *(const float4*)(b0 + cB);
    float4 gA = *(const float4*)(bn_g + cA), gB = *(const float4*)(bn_g + cB);
    float4 tA = *(const float4*)(bn_b + cA), tB = *(const float4*)(bn_b + cB);
    float4 mA = *(const float4*)(bn_m + cA), mB = *(const float4*)(bn_m + cB);
    float4 vA = *(const float4*)(bn_v + cA), vB = *(const float4*)(bn_v + cB);
    float4 oA, oB;
    oA.x = fmaxf((accA.x * invA + bA.x - mA.x) * (gA.x * rsqrtf(vA.x + 1e-5f)) + tA.x, 0.0f);
    oA.y = fmaxf((accA.y * invA + bA.y - mA.y) * (gA.y * rsqrtf(vA.y + 1e-5f)) + tA.y, 0.0f);
    oA.z = fmaxf((accA.z * invA + bA.z - mA.z) * (gA.z * rsqrtf(vA.z + 1e-5f)) + tA.z, 0.0f);
    oA.w = fmaxf((accA.w * invA + bA.w - mA.w) * (gA.w * rsqrtf(vA.w + 1e-5f)) + tA.w, 0.0f);
    oB.x = fmaxf((accB.x * invB + bB.x - mB.x) * (gB.x * rsqrtf(vB.x + 1e-5f)) + tB.x, 0.0f);
    oB.y = fmaxf((accB.y * invB + bB.y - mB.y) * (gB.y * rsqrtf(vB.y + 1e-5f)) + tB.y, 0.0f);
    oB.z = fmaxf((accB.z * invB + bB.z - mB.z) * (gB.z * rsqrtf(vB.z + 1e-5f)) + tB.z, 0.0f);
    oB.w = fmaxf((accB.w * invB + bB.w - mB.w) * (gB.w * rsqrtf(vB.w + 1e-5f)) + tB.w, 0.0f);
    float4* outr = (float4*)(g_hb + n * C0);
    outr[lane] = oA;
    outr[32 + lane] = oB;
}

// ---------------- layer1: CSR softmax + aggregate + b1 + colsum, warp per node ----------------
__global__ void agg1_csr(float* __restrict__ emb, const float* __restrict__ b1) {
    int w = (blockIdx.x * blockDim.x + threadIdx.x) >> 5;
    if (w >= NN) return;
    int lane = threadIdx.x & 31;
    int n = w;
    int beg = g_ptr[n], end = g_ptr[n + 1];
    float adn = g_ad1[n];

    float mx = -INFINITY;
    for (int i = beg + lane; i < end; i += 32) {
        int s = g_csr_src[i];
        mx = fmaxf(mx, leaky(g_as1[s] + adn));
    }
    #pragma unroll
    for (int off = 16; off >= 1; off >>= 1)
        mx = fmaxf(mx, __shfl_xor_sync(0xffffffffu, mx, off));

    float sum = 0.0f, acc = 0.0f;
    for (int i = beg; i < end; i++) {
        int s = g_csr_src[i];
        float wv = __expf(leaky(g_as1[s] + adn) - mx);
        sum += wv;
        acc += g_h1[s * C1 + lane] * wv;
    }
    float val = acc / sum + b1[lane];
    emb[n * C1 + lane] = val;
    atomicAdd(&g_gsum[lane], val);
}

// ---------------- prediction head ----------------
__global__ void predict_kernel(const float* __restrict__ hW1, const float* __restrict__ hb1,
                               const float* __restrict__ hW2, const float* __restrict__ hb2,
                               float* __restrict__ out, int pred_idx) {
    __shared__ float ge[C1];
    __shared__ float red[64];
    int t = threadIdx.x;
    if (t < C1) ge[t] = g_gsum[t] * (1.0f / (float)NN);
    __syncthreads();
    float s = hb1[t];
    #pragma unroll
    for (int c = 0; c < C1; c++) s += ge[c] * hW1[c * 64 + t];
    float v = fmaxf(s, 0.0f) * hW2[t];
    red[t] = v;
    __syncthreads();
    #pragma unroll
    for (int off = 32; off > 0; off >>= 1) {
        if (t < off) red[t] += red[t + off];
        __syncthreads();
    }
    if (t == 0) out[pred_idx] = red[0] + hb2[0];
}

// ---------------- launch ----------------
extern "C" void kernel_launch(void* const* d_in, const int* in_sizes, int n_in,
                              void* d_out, int out_size) {
    const float* x       = (const float*)d_in[0];
    const int*   ei      = (const int*)d_in[1];
    const float* W0      = (const float*)d_in[2];
    const float* a_src0  = (const float*)d_in[3];
    const float* a_dst0  = (const float*)d_in[4];
    const float* b0      = (const float*)d_in[5];
    const float* bn_g    = (const float*)d_in[6];
    const float* bn_b    = (const float*)d_in[7];
    const float* bn_m    = (const float*)d_in[8];
    const float* bn_v    = (const float*)d_in[9];
    const float* W1      = (const float*)d_in[10];
    const float* a_src1  = (const float*)d_in[11];
    const float* a_dst1  = (const float*)d_in[12];
    const float* b1      = (const float*)d_in[13];
    const float* hW1     = (const float*)d_in[14];
    const float* hb1     = (const float*)d_in[15];
    const float* hW2     = (const float*)d_in[16];
    const float* hb2     = (const float*)d_in[17];
    float* out = (float*)d_out;

    // CSR build
    init_kernel<<<256, 256>>>();
    hist_kernel<<<(EE + 255) / 256, 256>>>(ei);
    scan_kernel<<<1, 1024>>>();
    scatter_kernel<<<(ET + 255) / 256, 256>>>(ei);

    // layer 0
    {
        dim3 grid(C0 / 64, (NN + 63) / 64);
        gemm0_kernel<<<grid, 256>>>(x, W0, a_src0, a_dst0);
    }
    agg0_csr<<<(NN * 32 + 255) / 256, 256>>>(b0, bn_g, bn_b, bn_m, bn_v);

    // layer 1
    {
        dim3 grid(1, (NN + 63) / 64);
        gemm1_kernel<<<grid, 256>>>(W1, a_src1, a_dst1);
    }
    agg1_csr<<<(NN * 32 + 255) / 256, 256>>>(out, b1);
    predict_kernel<<<1, 64>>>(hW1, hb1, hW2, hb2, out, out_size - 1);
}

// round 5
// speedup vs baseline: 1.9461x; 1.3585x over previous
#include <cuda_runtime.h>
#include <cuda_bf16.h>
#include <math.h>

#define NN 50000
#define EE 800000
#define ET (EE + NN)      // edges + self loops
#define C0 256            // heads*hid = 4*64
#define H0 4
#define HD 64
#define C1 32
#define NEG 0.2f

// ---------------- device scratch ----------------
__device__ float g_h0[NN * C0];      // h0 = x@W0
__device__ float g_hb[NN * C0];      // layer0 output after agg+BN+ReLU
__device__ float g_as0[NN * H0];
__device__ float g_ad0[NN * H0];
__device__ float g_h1[NN * C1];
__device__ float g_as1[NN];
__device__ float g_ad1[NN];
__device__ float g_gsum[C1];
// CSR by destination
__device__ int g_cnt[NN];
__device__ int g_ptr[NN + 1];
__device__ int g_cur[NN];
__device__ int g_csr_src[ET];

// ---------------- f32x2 helpers ----------------
typedef unsigned long long u64t;
__device__ __forceinline__ u64t pack2(float lo, float hi) {
    u64t r; asm("mov.b64 %0, {%1, %2};" : "=l"(r) : "f"(lo), "f"(hi)); return r;
}
__device__ __forceinline__ void unpack2(u64t v, float& lo, float& hi) {
    asm("mov.b64 {%0, %1}, %2;" : "=f"(lo), "=f"(hi) : "l"(v));
}
__device__ __forceinline__ u64t fma2(u64t a, u64t b, u64t c) {
    u64t d; asm("fma.rn.f32x2 %0, %1, %2, %3;" : "=l"(d) : "l"(a), "l"(b), "l"(c)); return d;
}

// ---------------- init ----------------
__global__ void init_kernel() {
    int i = blockIdx.x * blockDim.x + threadIdx.x;
    int stride = gridDim.x * blockDim.x;
    for (int j = i; j < NN; j += stride) g_cnt[j] = 1;   // self loop
    if (i < C1) g_gsum[i] = 0.0f;
}

__global__ void hist_kernel(const int* __restrict__ ei) {
    int e = blockIdx.x * blockDim.x + threadIdx.x;
    if (e >= EE) return;
    atomicAdd(&g_cnt[ei[EE + e]], 1);
}

// single-block exclusive scan over 50K counts
__global__ void scan_kernel() {
    __shared__ int sums[1024];
    int t = threadIdx.x;
    const int CH = (NN + 1023) / 1024;
    int base = t * CH;
    int local = 0;
    for (int i = 0; i < CH; i++) {
        int idx = base + i;
        if (idx < NN) local += g_cnt[idx];
    }
    sums[t] = local;
    __syncthreads();
    for (int off = 1; off < 1024; off <<= 1) {
        int v = (t >= off) ? sums[t - off] : 0;
        __syncthreads();
        sums[t] += v;
        __syncthreads();
    }
    int run = sums[t] - local;
    for (int i = 0; i < CH; i++) {
        int idx = base + i;
        if (idx < NN) {
            g_ptr[idx] = run;
            g_cur[idx] = run;
            run += g_cnt[idx];
        }
    }
    if (t == 1023) g_ptr[NN] = run;
}

__global__ void scatter_kernel(const int* __restrict__ ei) {
    int e = blockIdx.x * blockDim.x + threadIdx.x;
    if (e >= ET) return;
    int s, d;
    if (e < EE) { s = ei[e]; d = ei[EE + e]; }
    else        { s = e - EE; d = s; }
    int pos = atomicAdd(&g_cur[d], 1);
    g_csr_src[pos] = s;
}

// ---------------- f32x2 GEMM core: BM x BN tile, 256 threads, 8x4 per thread ----------------
// accf[r][c] = C[brow + tr + r][bcol + tc + c]; also written to C.
template<int BM, int BN, int KDIM>
__device__ __forceinline__ void gemm_core(const float* __restrict__ A,
                                          const float* __restrict__ B,
                                          float* __restrict__ C,
                                          int M, int Ncol,
                                          float accf[8][4], int& tr_out, int& tc_out) {
    constexpr int BK = 16;
    constexpr int CG = BN / 4;              // col groups
    static_assert(BM * BN / 32 == 256, "256 threads");
    __shared__ float sA[BK][BM + 4];
    __shared__ float sB[BK][BN + 4];
    int tid = threadIdx.x;
    int brow = blockIdx.y * BM, bcol = blockIdx.x * BN;
    int tr = (tid / CG) * 8, tc = (tid % CG) * 4;
    tr_out = tr; tc_out = tc;

    u64t acc2[4][4];
    #pragma unroll
    for (int rp = 0; rp < 4; rp++)
        #pragma unroll
        for (int c = 0; c < 4; c++) acc2[rp][c] = 0ull;

    for (int k0 = 0; k0 < KDIM; k0 += BK) {
        // load A tile (BM x BK) transposed into sA
        #pragma unroll
        for (int i = tid; i < BM * (BK / 4); i += 256) {
            int r = i >> 2, cv = (i & 3) * 4;
            int gr = brow + r;
            float4 v = make_float4(0.f, 0.f, 0.f, 0.f);
            if (gr < M) v = *(const float4*)(A + gr * KDIM + k0 + cv);
            sA[cv][r] = v.x; sA[cv + 1][r] = v.y; sA[cv + 2][r] = v.z; sA[cv + 3][r] = v.w;
        }
        // load B tile (BK x BN)
        #pragma unroll
        for (int i = tid; i < BK * (BN / 4); i += 256) {
            int r = i / (BN / 4), cv = (i % (BN / 4)) * 4;
            *(float4*)(&sB[r][cv]) = *(const float4*)(B + (k0 + r) * Ncol + bcol + cv);
        }
        __syncthreads();
        #pragma unroll
        for (int kk = 0; kk < BK; kk++) {
            u64t a2[4];
            #pragma unroll
            for (int rp = 0; rp < 4; rp++)
                a2[rp] = *(const u64t*)(&sA[kk][tr + 2 * rp]);
            float4 bv = *(const float4*)(&sB[kk][tc]);
            u64t bd0 = pack2(bv.x, bv.x), bd1 = pack2(bv.y, bv.y);
            u64t bd2 = pack2(bv.z, bv.z), bd3 = pack2(bv.w, bv.w);
            #pragma unroll
            for (int rp = 0; rp < 4; rp++) {
                acc2[rp][0] = fma2(a2[rp], bd0, acc2[rp][0]);
                acc2[rp][1] = fma2(a2[rp], bd1, acc2[rp][1]);
                acc2[rp][2] = fma2(a2[rp], bd2, acc2[rp][2]);
                acc2[rp][3] = fma2(a2[rp], bd3, acc2[rp][3]);
            }
        }
        __syncthreads();
    }

    // unpack and write C
    #pragma unroll
    for (int rp = 0; rp < 4; rp++) {
        #pragma unroll
        for (int c = 0; c < 4; c++)
            unpack2(acc2[rp][c], accf[2 * rp][c], accf[2 * rp + 1][c]);
        int gr0 = brow + tr + 2 * rp;
        if (gr0 < M)
            *(float4*)(C + gr0 * Ncol + bcol + tc) =
                make_float4(accf[2 * rp][0], accf[2 * rp][1], accf[2 * rp][2], accf[2 * rp][3]);
        if (gr0 + 1 < M)
            *(float4*)(C + (gr0 + 1) * Ncol + bcol + tc) =
                make_float4(accf[2 * rp + 1][0], accf[2 * rp + 1][1], accf[2 * rp + 1][2], accf[2 * rp + 1][3]);
    }
}

// gemm0: x[50000,128] @ W0[128,256] -> g_h0, fused alpha0 (head = blockIdx.x)
__global__ void gemm0_kernel(const float* __restrict__ A, const float* __restrict__ B,
                             const float* __restrict__ a_src, const float* __restrict__ a_dst) {
    float accf[8][4];
    int tr, tc;
    gemm_core<128, 64, 128>(A, B, g_h0, NN, C0, accf, tr, tc);

    int head = blockIdx.x;
    int brow = blockIdx.y * 128;
    float as_p[8] = {}, ad_p[8] = {};
    #pragma unroll
    for (int c = 0; c < 4; c++) {
        float av = a_src[head * HD + tc + c];
        float dv = a_dst[head * HD + tc + c];
        #pragma unroll
        for (int r = 0; r < 8; r++) {
            as_p[r] += accf[r][c] * av;
            ad_p[r] += accf[r][c] * dv;
        }
    }
    #pragma unroll
    for (int off = 8; off >= 1; off >>= 1) {
        #pragma unroll
        for (int r = 0; r < 8; r++) {
            as_p[r] += __shfl_down_sync(0xffffffffu, as_p[r], off, 16);
            ad_p[r] += __shfl_down_sync(0xffffffffu, ad_p[r], off, 16);
        }
    }
    if ((threadIdx.x & 15) == 0) {
        #pragma unroll
        for (int r = 0; r < 8; r++) {
            int gr = brow + tr + r;
            if (gr < NN) {
                g_as0[gr * H0 + head] = as_p[r];
                g_ad0[gr * H0 + head] = ad_p[r];
            }
        }
    }
}

// gemm1: g_hb[50000,256] @ W1[256,32] -> g_h1, fused alpha1 (1 head)
__global__ void gemm1_kernel(const float* __restrict__ B,
                             const float* __restrict__ a_src, const float* __restrict__ a_dst) {
    float accf[8][4];
    int tr, tc;
    gemm_core<256, 32, 256>(g_hb, B, g_h1, NN, C1, accf, tr, tc);

    int brow = blockIdx.y * 256;
    float as_p[8] = {}, ad_p[8] = {};
    #pragma unroll
    for (int c = 0; c < 4; c++) {
        float av = a_src[tc + c];
        float dv = a_dst[tc + c];
        #pragma unroll
        for (int r = 0; r < 8; r++) {
            as_p[r] += accf[r][c] * av;
            ad_p[r] += accf[r][c] * dv;
        }
    }
    #pragma unroll
    for (int off = 4; off >= 1; off >>= 1) {
        #pragma unroll
        for (int r = 0; r < 8; r++) {
            as_p[r] += __shfl_down_sync(0xffffffffu, as_p[r], off, 8);
            ad_p[r] += __shfl_down_sync(0xffffffffu, ad_p[r], off, 8);
        }
    }
    if ((threadIdx.x & 7) == 0) {
        #pragma unroll
        for (int r = 0; r < 8; r++) {
            int gr = brow + tr + r;
            if (gr < NN) {
                g_as1[gr] = as_p[r];
                g_ad1[gr] = ad_p[r];
            }
        }
    }
}

__device__ __forceinline__ float leaky(float v) { return (v > 0.0f) ? v : NEG * v; }

// ---------------- layer0: CSR softmax + aggregate + bias + BN + ReLU, warp per node ----------------
__global__ void agg0_csr(const float* __restrict__ b0,
                         const float* __restrict__ bn_g, const float* __restrict__ bn_b,
                         const float* __restrict__ bn_m, const float* __restrict__ bn_v) {
    int w = (blockIdx.x * blockDim.x + threadIdx.x) >> 5;
    if (w >= NN) return;
    int lane = threadIdx.x & 31;
    int n = w;
    int beg = g_ptr[n], end = g_ptr[n + 1];

    float4 adn = *(const float4*)(g_ad0 + n * H0);
    float ad0 = adn.x, ad1 = adn.y, ad2 = adn.z, ad3 = adn.w;

    float m0 = -INFINITY, m1 = -INFINITY, m2 = -INFINITY, m3 = -INFINITY;
    for (int i = beg + lane; i < end; i += 32) {
        int s = g_csr_src[i];
        float4 av = *(const float4*)(g_as0 + s * H0);
        m0 = fmaxf(m0, leaky(av.x + ad0));
        m1 = fmaxf(m1, leaky(av.y + ad1));
        m2 = fmaxf(m2, leaky(av.z + ad2));
        m3 = fmaxf(m3, leaky(av.w + ad3));
    }
    #pragma unroll
    for (int off = 16; off >= 1; off >>= 1) {
        m0 = fmaxf(m0, __shfl_xor_sync(0xffffffffu, m0, off));
        m1 = fmaxf(m1, __shfl_xor_sync(0xffffffffu, m1, off));
        m2 = fmaxf(m2, __shfl_xor_sync(0xffffffffu, m2, off));
        m3 = fmaxf(m3, __shfl_xor_sync(0xffffffffu, m3, off));
    }

    float s0 = 0, s1 = 0, s2 = 0, s3 = 0;
    float4 accA = {0, 0, 0, 0}, accB = {0, 0, 0, 0};
    int hA = lane >> 4;
    for (int i = beg; i < end; i++) {
        int s = g_csr_src[i];
        float4 av = *(const float4*)(g_as0 + s * H0);
        float w0 = __expf(leaky(av.x + ad0) - m0);
        float w1 = __expf(leaky(av.y + ad1) - m1);
        float w2 = __expf(leaky(av.z + ad2) - m2);
        float w3 = __expf(leaky(av.w + ad3) - m3);
        s0 += w0; s1 += w1; s2 += w2; s3 += w3;
        const float4* hr = (const float4*)(g_h0 + s * C0);
        float4 v0 = hr[lane];
        float4 v1 = hr[32 + lane];
        float wa = hA ? w1 : w0;
        float wb = hA ? w3 : w2;
        accA.x += v0.x * wa; accA.y += v0.y * wa; accA.z += v0.z * wa; accA.w += v0.w * wa;
        accB.x += v1.x * wb; accB.y += v1.y * wb; accB.z += v1.z * wb; accB.w += v1.w * wb;
    }
    float invA = 1.0f / (hA ? s1 : s0);
    float invB = 1.0f / (hA ? s3 : s2);

    int cA = 4 * lane, cB = 128 + 4 * lane;
    float4 bA = *(const float4*)(b0 + cA),   bB = *(const float4*)(b0 + cB);
    float4 gA = *(const float4*)(bn_g + cA), gB = *(const float4*)(bn_g + cB);
    float4 tA = *(const float4*)(bn_b + cA), tB = *(const float4*)(bn_b + cB);
    float4 mA = *(const float4*)(bn_m + cA), mB = *(const float4*)(bn_m + cB);
    float4 vA = *(const float4*)(bn_v + cA), vB = *(const float4*)(bn_v + cB);
    float4 oA, oB;
    oA.x = fmaxf((accA.x * invA + bA.x - mA.x) * (gA.x * rsqrtf(vA.x + 1e-5f)) + tA.x, 0.0f);
    oA.y = fmaxf((accA.y * invA + bA.y - mA.y) * (gA.y * rsqrtf(vA.y + 1e-5f)) + tA.y, 0.0f);
    oA.z = fmaxf((accA.z * invA + bA.z - mA.z) * (gA.z * rsqrtf(vA.z + 1e-5f)) + tA.z, 0.0f);
    oA.w = fmaxf((accA.w * invA + bA.w - mA.w) * (gA.w * rsqrtf(vA.w + 1e-5f)) + tA.w, 0.0f);
    oB.x = fmaxf((accB.x * invB + bB.x - mB.x) * (gB.x * rsqrtf(vB.x + 1e-5f)) + tB.x, 0.0f);
    oB.y = fmaxf((accB.y * invB + bB.y - mB.y) * (gB.y * rsqrtf(vB.y + 1e-5f)) + tB.y, 0.0f);
    oB.z = fmaxf((accB.z * invB + bB.z - mB.z) * (gB.z * rsqrtf(vB.z + 1e-5f)) + tB.z, 0.0f);
    oB.w = fmaxf((accB.w * invB + bB.w - mB.w) * (gB.w * rsqrtf(vB.w + 1e-5f)) + tB.w, 0.0f);
    float4* outr = (float4*)(g_hb + n * C0);
    outr[lane] = oA;
    outr[32 + lane] = oB;
}

// ---------------- layer1: CSR softmax + aggregate + b1 + colsum, warp per node ----------------
__global__ void agg1_csr(float* __restrict__ emb, const float* __restrict__ b1) {
    int w = (blockIdx.x * blockDim.x + threadIdx.x) >> 5;
    if (w >= NN) return;
    int lane = threadIdx.x & 31;
    int n = w;
    int beg = g_ptr[n], end = g_ptr[n + 1];
    float adn = g_ad1[n];

    float mx = -INFINITY;
    for (int i = beg + lane; i < end; i += 32) {
        int s = g_csr_src[i];
        mx = fmaxf(mx, leaky(g_as1[s] + adn));
    }
    #pragma unroll
    for (int off = 16; off >= 1; off >>= 1)
        mx = fmaxf(mx, __shfl_xor_sync(0xffffffffu, mx, off));

    float sum = 0.0f, acc = 0.0f;
    for (int i = beg; i < end; i++) {
        int s = g_csr_src[i];
        float wv = __expf(leaky(g_as1[s] + adn) - mx);
        sum += wv;
        acc += g_h1[s * C1 + lane] * wv;
    }
    float val = acc / sum + b1[lane];
    emb[n * C1 + lane] = val;
    atomicAdd(&g_gsum[lane], val);
}

// ---------------- prediction head ----------------
__global__ void predict_kernel(const float* __restrict__ hW1, const float* __restrict__ hb1,
                               const float* __restrict__ hW2, const float* __restrict__ hb2,
                               float* __restrict__ out, int pred_idx) {
    __shared__ float ge[C1];
    __shared__ float red[64];
    int t = threadIdx.x;
    if (t < C1) ge[t] = g_gsum[t] * (1.0f / (float)NN);
    __syncthreads();
    float s = hb1[t];
    #pragma unroll
    for (int c = 0; c < C1; c++) s += ge[c] * hW1[c * 64 + t];
    float v = fmaxf(s, 0.0f) * hW2[t];
    red[t] = v;
    __syncthreads();
    #pragma unroll
    for (int off = 32; off > 0; off >>= 1) {
        if (t < off) red[t] += red[t + off];
        __syncthreads();
    }
    if (t == 0) out[pred_idx] = red[0] + hb2[0];
}

// ---------------- launch ----------------
extern "C" void kernel_launch(void* const* d_in, const int* in_sizes, int n_in,
                              void* d_out, int out_size) {
    const float* x       = (const float*)d_in[0];
    const int*   ei      = (const int*)d_in[1];
    const float* W0      = (const float*)d_in[2];
    const float* a_src0  = (const float*)d_in[3];
    const float* a_dst0  = (const float*)d_in[4];
    const float* b0      = (const float*)d_in[5];
    const float* bn_g    = (const float*)d_in[6];
    const float* bn_b    = (const float*)d_in[7];
    const float* bn_m    = (const float*)d_in[8];
    const float* bn_v    = (const float*)d_in[9];
    const float* W1      = (const float*)d_in[10];
    const float* a_src1  = (const float*)d_in[11];
    const float* a_dst1  = (const float*)d_in[12];
    const float* b1      = (const float*)d_in[13];
    const float* hW1     = (const float*)d_in[14];
    const float* hb1     = (const float*)d_in[15];
    const float* hW2     = (const float*)d_in[16];
    const float* hb2     = (const float*)d_in[17];
    float* out = (float*)d_out;

    // CSR build
    init_kernel<<<256, 256>>>();
    hist_kernel<<<(EE + 255) / 256, 256>>>(ei);
    scan_kernel<<<1, 1024>>>();
    scatter_kernel<<<(ET + 255) / 256, 256>>>(ei);

    // layer 0
    {
        dim3 grid(C0 / 64, (NN + 127) / 128);
        gemm0_kernel<<<grid, 256>>>(x, W0, a_src0, a_dst0);
    }
    agg0_csr<<<(NN * 32 + 255) / 256, 256>>>(b0, bn_g, bn_b, bn_m, bn_v);

    // layer 1
    {
        dim3 grid(1, (NN + 255) / 256);
        gemm1_kernel<<<grid, 256>>>(W1, a_src1, a_dst1);
    }
    agg1_csr<<<(NN * 32 + 255) / 256, 256>>>(out, b1);
    predict_kernel<<<1, 64>>>(hW1, hb1, hW2, hb2, out, out_size - 1);
}

// round 6
// speedup vs baseline: 2.2140x; 1.1377x over previous
#include <cuda_runtime.h>
#include <cuda_bf16.h>
#include <math.h>

#define NN 50000
#define EE 800000
#define ET (EE + NN)
#define C0 256
#define H0 4
#define HD 64
#define C1 32
#define NEG 0.2f

// ---------------- device scratch ----------------
__device__ float g_h0[NN * C0];
__device__ float g_hb[NN * C0];
__device__ float g_as0[NN * H0];
__device__ float g_ad0[NN * H0];
__device__ float g_h1[NN * C1];
__device__ float g_as1[NN];
__device__ float g_ad1[NN];
__device__ float g_gsum[C1];
__device__ int g_cnt[NN];
__device__ int g_ptr[NN + 1];
__device__ int g_cur[NN];
__device__ int g_csr_src[ET];

// ---------------- tf32 helpers ----------------
__device__ __forceinline__ float tf32r(float f) {
    unsigned int u;
    asm("cvt.rna.tf32.f32 %0, %1;" : "=r"(u) : "f"(f));
    return __uint_as_float(u);
}
__device__ __forceinline__ void mma_tf32(float& d0, float& d1, float& d2, float& d3,
                                         unsigned a0, unsigned a1, unsigned a2, unsigned a3,
                                         unsigned b0, unsigned b1) {
    asm volatile("mma.sync.aligned.m16n8k8.row.col.f32.tf32.tf32.f32 "
                 "{%0,%1,%2,%3}, {%4,%5,%6,%7}, {%8,%9}, {%0,%1,%2,%3};"
                 : "+f"(d0), "+f"(d1), "+f"(d2), "+f"(d3)
                 : "r"(a0), "r"(a1), "r"(a2), "r"(a3), "r"(b0), "r"(b1));
}

// ---------------- CSR build ----------------
__global__ void init_kernel() {
    int i = blockIdx.x * blockDim.x + threadIdx.x;
    int stride = gridDim.x * blockDim.x;
    for (int j = i; j < NN; j += stride) g_cnt[j] = 1;
    if (i < C1) g_gsum[i] = 0.0f;
}

__global__ void hist_kernel(const int* __restrict__ ei) {
    int e = blockIdx.x * blockDim.x + threadIdx.x;
    if (e >= EE) return;
    atomicAdd(&g_cnt[ei[EE + e]], 1);
}

__global__ void scan_kernel() {
    __shared__ int sums[1024];
    int t = threadIdx.x;
    const int CH = (NN + 1023) / 1024;
    int base = t * CH;
    int local = 0;
    for (int i = 0; i < CH; i++) {
        int idx = base + i;
        if (idx < NN) local += g_cnt[idx];
    }
    sums[t] = local;
    __syncthreads();
    for (int off = 1; off < 1024; off <<= 1) {
        int v = (t >= off) ? sums[t - off] : 0;
        __syncthreads();
        sums[t] += v;
        __syncthreads();
    }
    int run = sums[t] - local;
    for (int i = 0; i < CH; i++) {
        int idx = base + i;
        if (idx < NN) {
            g_ptr[idx] = run;
            g_cur[idx] = run;
            run += g_cnt[idx];
        }
    }
    if (t == 1023) g_ptr[NN] = run;
}

__global__ void scatter_kernel(const int* __restrict__ ei) {
    int e = blockIdx.x * blockDim.x + threadIdx.x;
    if (e >= ET) return;
    int s, d;
    if (e < EE) { s = ei[e]; d = ei[EE + e]; }
    else        { s = e - EE; d = s; }
    int pos = atomicAdd(&g_cur[d], 1);
    g_csr_src[pos] = s;
}

// ================= gemm0: x[NN,128] @ W0[128,256] -> g_h0, fused alpha0 =================
// 256 threads, tile 128x64 (one head per blockIdx.x), warps 4x2, warp tile 32x32, BK=16
#define SA_S 20
#define SB_S 72
__global__ void gemm0_kernel(const float* __restrict__ A, const float* __restrict__ B,
                             const float* __restrict__ a_src, const float* __restrict__ a_dst) {
    __shared__ float sA[128 * SA_S];
    __shared__ float sB[16 * SB_S];
    __shared__ float s_as[128], s_ad[128];
    int tid = threadIdx.x;
    int wid = tid >> 5, lane = tid & 31;
    int gid = lane >> 2, tig = lane & 3;       // groupID, thread-in-group
    int warp_m = wid >> 1, warp_n = wid & 1;
    int head = blockIdx.x;
    int brow = blockIdx.y * 128, bcol = head * 64;

    float acc[2][4][4];
    #pragma unroll
    for (int mt = 0; mt < 2; mt++)
        #pragma unroll
        for (int nt = 0; nt < 4; nt++)
            #pragma unroll
            for (int q = 0; q < 4; q++) acc[mt][nt][q] = 0.0f;

    for (int k0 = 0; k0 < 128; k0 += 16) {
        // A tile 128x16 (tf32-converted)
        #pragma unroll
        for (int i = tid; i < 128 * 4; i += 256) {
            int r = i >> 2, cq = (i & 3) * 4;
            int gr = brow + r;
            float4 v = make_float4(0.f, 0.f, 0.f, 0.f);
            if (gr < NN) v = *(const float4*)(A + gr * 128 + k0 + cq);
            sA[r * SA_S + cq]     = tf32r(v.x);
            sA[r * SA_S + cq + 1] = tf32r(v.y);
            sA[r * SA_S + cq + 2] = tf32r(v.z);
            sA[r * SA_S + cq + 3] = tf32r(v.w);
        }
        // B tile 16x64
        #pragma unroll
        for (int i = tid; i < 16 * 16; i += 256) {
            int r = i >> 4, cq = (i & 15) * 4;
            float4 v = *(const float4*)(B + (k0 + r) * C0 + bcol + cq);
            sB[r * SB_S + cq]     = tf32r(v.x);
            sB[r * SB_S + cq + 1] = tf32r(v.y);
            sB[r * SB_S + cq + 2] = tf32r(v.z);
            sB[r * SB_S + cq + 3] = tf32r(v.w);
        }
        __syncthreads();
        #pragma unroll
        for (int ks = 0; ks < 16; ks += 8) {
            unsigned af[2][4];
            #pragma unroll
            for (int mt = 0; mt < 2; mt++) {
                int r0 = (warp_m * 32 + mt * 16 + gid) * SA_S;
                af[mt][0] = __float_as_uint(sA[r0 + ks + tig]);
                af[mt][1] = __float_as_uint(sA[r0 + 8 * SA_S + ks + tig]);
                af[mt][2] = __float_as_uint(sA[r0 + ks + tig + 4]);
                af[mt][3] = __float_as_uint(sA[r0 + 8 * SA_S + ks + tig + 4]);
            }
            unsigned bf[4][2];
            #pragma unroll
            for (int nt = 0; nt < 4; nt++) {
                int col = warp_n * 32 + nt * 8 + gid;
                bf[nt][0] = __float_as_uint(sB[(ks + tig) * SB_S + col]);
                bf[nt][1] = __float_as_uint(sB[(ks + tig + 4) * SB_S + col]);
            }
            #pragma unroll
            for (int mt = 0; mt < 2; mt++)
                #pragma unroll
                for (int nt = 0; nt < 4; nt++)
                    mma_tf32(acc[mt][nt][0], acc[mt][nt][1], acc[mt][nt][2], acc[mt][nt][3],
                             af[mt][0], af[mt][1], af[mt][2], af[mt][3],
                             bf[nt][0], bf[nt][1]);
        }
        __syncthreads();
    }

    // store h0 + alpha partials
    if (tid < 128) { s_as[tid] = 0.0f; s_ad[tid] = 0.0f; }
    __syncthreads();

    float asp[2][2] = {}, adp[2][2] = {};
    #pragma unroll
    for (int mt = 0; mt < 2; mt++) {
        int r0 = brow + warp_m * 32 + mt * 16 + gid;
        #pragma unroll
        for (int nt = 0; nt < 4; nt++) {
            int hcol = warp_n * 32 + nt * 8 + tig * 2;
            float av0 = a_src[head * HD + hcol],  av1 = a_src[head * HD + hcol + 1];
            float dv0 = a_dst[head * HD + hcol],  dv1 = a_dst[head * HD + hcol + 1];
            float d0 = acc[mt][nt][0], d1 = acc[mt][nt][1];
            float d2 = acc[mt][nt][2], d3 = acc[mt][nt][3];
            asp[mt][0] += d0 * av0 + d1 * av1;
            asp[mt][1] += d2 * av0 + d3 * av1;
            adp[mt][0] += d0 * dv0 + d1 * dv1;
            adp[mt][1] += d2 * dv0 + d3 * dv1;
            int col = bcol + hcol;
            if (r0 < NN)     *(float2*)(g_h0 + r0 * C0 + col)       = make_float2(d0, d1);
            if (r0 + 8 < NN) *(float2*)(g_h0 + (r0 + 8) * C0 + col) = make_float2(d2, d3);
        }
    }
    #pragma unroll
    for (int off = 1; off <= 2; off <<= 1) {
        #pragma unroll
        for (int mt = 0; mt < 2; mt++) {
            asp[mt][0] += __shfl_xor_sync(0xffffffffu, asp[mt][0], off);
            asp[mt][1] += __shfl_xor_sync(0xffffffffu, asp[mt][1], off);
            adp[mt][0] += __shfl_xor_sync(0xffffffffu, adp[mt][0], off);
            adp[mt][1] += __shfl_xor_sync(0xffffffffu, adp[mt][1], off);
        }
    }
    if (tig == 0) {
        #pragma unroll
        for (int mt = 0; mt < 2; mt++) {
            int lr = warp_m * 32 + mt * 16 + gid;
            atomicAdd(&s_as[lr], asp[mt][0]);
            atomicAdd(&s_as[lr + 8], asp[mt][1]);
            atomicAdd(&s_ad[lr], adp[mt][0]);
            atomicAdd(&s_ad[lr + 8], adp[mt][1]);
        }
    }
    __syncthreads();
    if (tid < 128) {
        int gr = brow + tid;
        if (gr < NN) {
            g_as0[gr * H0 + head] = s_as[tid];
            g_ad0[gr * H0 + head] = s_ad[tid];
        }
    }
}

// ================= gemm1: g_hb[NN,256] @ W1[256,32] -> g_h1, fused alpha1 =================
// 256 threads, tile 128x32, 8 row-warps x 16 rows, BK=16
#define SB1_S 40
__global__ void gemm1_kernel(const float* __restrict__ B,
                             const float* __restrict__ a_src, const float* __restrict__ a_dst) {
    __shared__ float sA[128 * SA_S];
    __shared__ float sB[16 * SB1_S];
    int tid = threadIdx.x;
    int wid = tid >> 5, lane = tid & 31;
    int gid = lane >> 2, tig = lane & 3;
    int brow = blockIdx.y * 128;

    float acc[4][4];
    #pragma unroll
    for (int nt = 0; nt < 4; nt++)
        #pragma unroll
        for (int q = 0; q < 4; q++) acc[nt][q] = 0.0f;

    for (int k0 = 0; k0 < 256; k0 += 16) {
        #pragma unroll
        for (int i = tid; i < 128 * 4; i += 256) {
            int r = i >> 2, cq = (i & 3) * 4;
            int gr = brow + r;
            float4 v = make_float4(0.f, 0.f, 0.f, 0.f);
            if (gr < NN) v = *(const float4*)(g_hb + gr * C0 + k0 + cq);
            sA[r * SA_S + cq]     = tf32r(v.x);
            sA[r * SA_S + cq + 1] = tf32r(v.y);
            sA[r * SA_S + cq + 2] = tf32r(v.z);
            sA[r * SA_S + cq + 3] = tf32r(v.w);
        }
        if (tid < 128) {
            int r = tid >> 3, cq = (tid & 7) * 4;
            float4 v = *(const float4*)(B + (k0 + r) * C1 + cq);
            sB[r * SB1_S + cq]     = tf32r(v.x);
            sB[r * SB1_S + cq + 1] = tf32r(v.y);
            sB[r * SB1_S + cq + 2] = tf32r(v.z);
            sB[r * SB1_S + cq + 3] = tf32r(v.w);
        }
        __syncthreads();
        #pragma unroll
        for (int ks = 0; ks < 16; ks += 8) {
            int r0 = (wid * 16 + gid) * SA_S;
            unsigned a0 = __float_as_uint(sA[r0 + ks + tig]);
            unsigned a1 = __float_as_uint(sA[r0 + 8 * SA_S + ks + tig]);
            unsigned a2 = __float_as_uint(sA[r0 + ks + tig + 4]);
            unsigned a3 = __float_as_uint(sA[r0 + 8 * SA_S + ks + tig + 4]);
            #pragma unroll
            for (int nt = 0; nt < 4; nt++) {
                int col = nt * 8 + gid;
                unsigned b0 = __float_as_uint(sB[(ks + tig) * SB1_S + col]);
                unsigned b1 = __float_as_uint(sB[(ks + tig + 4) * SB1_S + col]);
                mma_tf32(acc[nt][0], acc[nt][1], acc[nt][2], acc[nt][3],
                         a0, a1, a2, a3, b0, b1);
            }
        }
        __syncthreads();
    }

    int r0 = brow + wid * 16 + gid;
    float as0 = 0, as1 = 0, ad0 = 0, ad1 = 0;
    #pragma unroll
    for (int nt = 0; nt < 4; nt++) {
        int col = nt * 8 + tig * 2;
        float av0 = a_src[col], av1 = a_src[col + 1];
        float dv0 = a_dst[col], dv1 = a_dst[col + 1];
        float d0 = acc[nt][0], d1 = acc[nt][1], d2 = acc[nt][2], d3 = acc[nt][3];
        as0 += d0 * av0 + d1 * av1;
        as1 += d2 * av0 + d3 * av1;
        ad0 += d0 * dv0 + d1 * dv1;
        ad1 += d2 * dv0 + d3 * dv1;
        if (r0 < NN)     *(float2*)(g_h1 + r0 * C1 + col)       = make_float2(d0, d1);
        if (r0 + 8 < NN) *(float2*)(g_h1 + (r0 + 8) * C1 + col) = make_float2(d2, d3);
    }
    #pragma unroll
    for (int off = 1; off <= 2; off <<= 1) {
        as0 += __shfl_xor_sync(0xffffffffu, as0, off);
        as1 += __shfl_xor_sync(0xffffffffu, as1, off);
        ad0 += __shfl_xor_sync(0xffffffffu, ad0, off);
        ad1 += __shfl_xor_sync(0xffffffffu, ad1, off);
    }
    if (tig == 0) {
        if (r0 < NN)     { g_as1[r0] = as0;     g_ad1[r0] = ad0; }
        if (r0 + 8 < NN) { g_as1[r0 + 8] = as1; g_ad1[r0 + 8] = ad1; }
    }
}

__device__ __forceinline__ float leaky(float v) { return (v > 0.0f) ? v : NEG * v; }

// ---------------- layer0: CSR softmax + aggregate + bias + BN + ReLU, warp per node ----------------
__global__ void agg0_csr(const float* __restrict__ b0,
                         const float* __restrict__ bn_g, const float* __restrict__ bn_b,
                         const float* __restrict__ bn_m, const float* __restrict__ bn_v) {
    int w = (blockIdx.x * blockDim.x + threadIdx.x) >> 5;
    if (w >= NN) return;
    int lane = threadIdx.x & 31;
    int n = w;
    int beg = g_ptr[n], end = g_ptr[n + 1];

    float4 adn = *(const float4*)(g_ad0 + n * H0);
    float ad0 = adn.x, ad1 = adn.y, ad2 = adn.z, ad3 = adn.w;

    float m0 = -INFINITY, m1 = -INFINITY, m2 = -INFINITY, m3 = -INFINITY;
    for (int i = beg + lane; i < end; i += 32) {
        int s = g_csr_src[i];
        float4 av = *(const float4*)(g_as0 + s * H0);
        m0 = fmaxf(m0, leaky(av.x + ad0));
        m1 = fmaxf(m1, leaky(av.y + ad1));
        m2 = fmaxf(m2, leaky(av.z + ad2));
        m3 = fmaxf(m3, leaky(av.w + ad3));
    }
    #pragma unroll
    for (int off = 16; off >= 1; off >>= 1) {
        m0 = fmaxf(m0, __shfl_xor_sync(0xffffffffu, m0, off));
        m1 = fmaxf(m1, __shfl_xor_sync(0xffffffffu, m1, off));
        m2 = fmaxf(m2, __shfl_xor_sync(0xffffffffu, m2, off));
        m3 = fmaxf(m3, __shfl_xor_sync(0xffffffffu, m3, off));
    }

    float s0 = 0, s1 = 0, s2 = 0, s3 = 0;
    float4 accA = {0, 0, 0, 0}, accB = {0, 0, 0, 0};
    int hA = lane >> 4;
    for (int i = beg; i < end; i++) {
        int s = g_csr_src[i];
        float4 av = *(const float4*)(g_as0 + s * H0);
        float w0 = __expf(leaky(av.x + ad0) - m0);
        float w1 = __expf(leaky(av.y + ad1) - m1);
        float w2 = __expf(leaky(av.z + ad2) - m2);
        float w3 = __expf(leaky(av.w + ad3) - m3);
        s0 += w0; s1 += w1; s2 += w2; s3 += w3;
        const float4* hr = (const float4*)(g_h0 + s * C0);
        float4 v0 = hr[lane];
        float4 v1 = hr[32 + lane];
        float wa = hA ? w1 : w0;
        float wb = hA ? w3 : w2;
        accA.x += v0.x * wa; accA.y += v0.y * wa; accA.z += v0.z * wa; accA.w += v0.w * wa;
        accB.x += v1.x * wb; accB.y += v1.y * wb; accB.z += v1.z * wb; accB.w += v1.w * wb;
    }
    float invA = 1.0f / (hA ? s1 : s0);
    float invB = 1.0f / (hA ? s3 : s2);

    int cA = 4 * lane, cB = 128 + 4 * lane;
    float4 bA = *(const float4*)(b0 + cA),   bB = *(const float4*)(b0 + cB);
    float4 gA = *(const float4*)(bn_g + cA), gB = *(const float4*)(bn_g + cB);
    float4 tA = *(const float4*)(bn_b + cA), tB = *(const float4*)(bn_b + cB);
    float4 mA = *(const float4*)(bn_m + cA), mB = *(const float4*)(bn_m + cB);
    float4 vA = *(const float4*)(bn_v + cA), vB = *(const float4*)(bn_v + cB);
    float4 oA, oB;
    oA.x = fmaxf((accA.x * invA + bA.x - mA.x) * (gA.x * rsqrtf(vA.x + 1e-5f)) + tA.x, 0.0f);
    oA.y = fmaxf((accA.y * invA + bA.y - mA.y) * (gA.y * rsqrtf(vA.y + 1e-5f)) + tA.y, 0.0f);
    oA.z = fmaxf((accA.z * invA + bA.z - mA.z) * (gA.z * rsqrtf(vA.z + 1e-5f)) + tA.z, 0.0f);
    oA.w = fmaxf((accA.w * invA + bA.w - mA.w) * (gA.w * rsqrtf(vA.w + 1e-5f)) + tA.w, 0.0f);
    oB.x = fmaxf((accB.x * invB + bB.x - mB.x) * (gB.x * rsqrtf(vB.x + 1e-5f)) + tB.x, 0.0f);
    oB.y = fmaxf((accB.y * invB + bB.y - mB.y) * (gB.y * rsqrtf(vB.y + 1e-5f)) + tB.y, 0.0f);
    oB.z = fmaxf((accB.z * invB + bB.z - mB.z) * (gB.z * rsqrtf(vB.z + 1e-5f)) + tB.z, 0.0f);
    oB.w = fmaxf((accB.w * invB + bB.w - mB.w) * (gB.w * rsqrtf(vB.w + 1e-5f)) + tB.w, 0.0f);
    float4* outr = (float4*)(g_hb + n * C0);
    outr[lane] = oA;
    outr[32 + lane] = oB;
}

// ---------------- layer1: CSR softmax + aggregate + b1 + colsum ----------------
__global__ void agg1_csr(float* __restrict__ emb, const float* __restrict__ b1) {
    int w = (blockIdx.x * blockDim.x + threadIdx.x) >> 5;
    if (w >= NN) return;
    int lane = threadIdx.x & 31;
    int n = w;
    int beg = g_ptr[n], end = g_ptr[n + 1];
    float adn = g_ad1[n];

    float mx = -INFINITY;
    for (int i = beg + lane; i < end; i += 32) {
        int s = g_csr_src[i];
        mx = fmaxf(mx, leaky(g_as1[s] + adn));
    }
    #pragma unroll
    for (int off = 16; off >= 1; off >>= 1)
        mx = fmaxf(mx, __shfl_xor_sync(0xffffffffu, mx, off));

    float sum = 0.0f, acc = 0.0f;
    for (int i = beg; i < end; i++) {
        int s = g_csr_src[i];
        float wv = __expf(leaky(g_as1[s] + adn) - mx);
        sum += wv;
        acc += g_h1[s * C1 + lane] * wv;
    }
    float val = acc / sum + b1[lane];
    emb[n * C1 + lane] = val;
    atomicAdd(&g_gsum[lane], val);
}

// ---------------- prediction head ----------------
__global__ void predict_kernel(const float* __restrict__ hW1, const float* __restrict__ hb1,
                               const float* __restrict__ hW2, const float* __restrict__ hb2,
                               float* __restrict__ out, int pred_idx) {
    __shared__ float ge[C1];
    __shared__ float red[64];
    int t = threadIdx.x;
    if (t < C1) ge[t] = g_gsum[t] * (1.0f / (float)NN);
    __syncthreads();
    float s = hb1[t];
    #pragma unroll
    for (int c = 0; c < C1; c++) s += ge[c] * hW1[c * 64 + t];
    float v = fmaxf(s, 0.0f) * hW2[t];
    red[t] = v;
    __syncthreads();
    #pragma unroll
    for (int off = 32; off > 0; off >>= 1) {
        if (t < off) red[t] += red[t + off];
        __syncthreads();
    }
    if (t == 0) out[pred_idx] = red[0] + hb2[0];
}

// ---------------- launch ----------------
extern "C" void kernel_launch(void* const* d_in, const int* in_sizes, int n_in,
                              void* d_out, int out_size) {
    const float* x       = (const float*)d_in[0];
    const int*   ei      = (const int*)d_in[1];
    const float* W0      = (const float*)d_in[2];
    const float* a_src0  = (const float*)d_in[3];
    const float* a_dst0  = (const float*)d_in[4];
    const float* b0      = (const float*)d_in[5];
    const float* bn_g    = (const float*)d_in[6];
    const float* bn_b    = (const float*)d_in[7];
    const float* bn_m    = (const float*)d_in[8];
    const float* bn_v    = (const float*)d_in[9];
    const float* W1      = (const float*)d_in[10];
    const float* a_src1  = (const float*)d_in[11];
    const float* a_dst1  = (const float*)d_in[12];
    const float* b1      = (const float*)d_in[13];
    const float* hW1     = (const float*)d_in[14];
    const float* hb1     = (const float*)d_in[15];
    const float* hW2     = (const float*)d_in[16];
    const float* hb2     = (const float*)d_in[17];
    float* out = (float*)d_out;

    init_kernel<<<256, 256>>>();
    hist_kernel<<<(EE + 255) / 256, 256>>>(ei);
    scan_kernel<<<1, 1024>>>();
    scatter_kernel<<<(ET + 255) / 256, 256>>>(ei);

    {
        dim3 grid(4, (NN + 127) / 128);
        gemm0_kernel<<<grid, 256>>>(x, W0, a_src0, a_dst0);
    }
    agg0_csr<<<(NN * 32 + 255) / 256, 256>>>(b0, bn_g, bn_b, bn_m, bn_v);

    {
        dim3 grid(1, (NN + 127) / 128);
        gemm1_kernel<<<grid, 256>>>(W1, a_src1, a_dst1);
    }
    agg1_csr<<<(NN * 32 + 255) / 256, 256>>>(out, b1);
    predict_kernel<<<1, 64>>>(hW1, hb1, hW2, hb2, out, out_size - 1);
}

// round 7
// speedup vs baseline: 2.6137x; 1.1805x over previous
#include <cuda_runtime.h>
#include <cuda_bf16.h>
#include <cuda_fp16.h>
#include <math.h>

#define NN 50000
#define EE 800000
#define ET (EE + NN)
#define C0 256
#define H0 4
#define HD 64
#define C1 32
#define NEG 0.2f

#define NBG0 (4 * ((NN + 127) / 128))   // 1564 gemm0 blocks
#define HBLK 256                        // hist blocks fused after gemm0 blocks

// ---------------- device scratch ----------------
__device__ __half g_h0h[NN * C0];    // h0 (fp16) for agg0 gather
__device__ __half g_hbh[NN * C0];    // layer0 output (fp16) for gemm1
__device__ float g_as0[NN * H0];
__device__ float g_ad0[NN * H0];
__device__ float g_h1[NN * C1];
__device__ float g_as1[NN];
__device__ float g_ad1[NN];
__device__ float g_gsum[C1];
__device__ int g_cnt[NN];
__device__ int g_ptr[NN + 1];
__device__ int g_cur[NN];
__device__ int g_csr_src[ET];

// ---------------- tf32 helpers ----------------
__device__ __forceinline__ float tf32r(float f) {
    unsigned int u;
    asm("cvt.rna.tf32.f32 %0, %1;" : "=r"(u) : "f"(f));
    return __uint_as_float(u);
}
__device__ __forceinline__ void mma_tf32(float& d0, float& d1, float& d2, float& d3,
                                         unsigned a0, unsigned a1, unsigned a2, unsigned a3,
                                         unsigned b0, unsigned b1) {
    asm volatile("mma.sync.aligned.m16n8k8.row.col.f32.tf32.tf32.f32 "
                 "{%0,%1,%2,%3}, {%4,%5,%6,%7}, {%8,%9}, {%0,%1,%2,%3};"
                 : "+f"(d0), "+f"(d1), "+f"(d2), "+f"(d3)
                 : "r"(a0), "r"(a1), "r"(a2), "r"(a3), "r"(b0), "r"(b1));
}

__device__ __forceinline__ float leaky(float v) { return (v > 0.0f) ? v : NEG * v; }

// ---------------- CSR build ----------------
__global__ void init_kernel() {
    int i = blockIdx.x * blockDim.x + threadIdx.x;
    int stride = gridDim.x * blockDim.x;
    for (int j = i; j < NN; j += stride) g_cnt[j] = 1;   // self loop
    if (i < C1) g_gsum[i] = 0.0f;
}

__global__ void scan_kernel() {
    __shared__ int sums[1024];
    int t = threadIdx.x;
    const int CH = (NN + 1023) / 1024;
    int base = t * CH;
    int local = 0;
    for (int i = 0; i < CH; i++) {
        int idx = base + i;
        if (idx < NN) local += g_cnt[idx];
    }
    sums[t] = local;
    __syncthreads();
    for (int off = 1; off < 1024; off <<= 1) {
        int v = (t >= off) ? sums[t - off] : 0;
        __syncthreads();
        sums[t] += v;
        __syncthreads();
    }
    int run = sums[t] - local;
    for (int i = 0; i < CH; i++) {
        int idx = base + i;
        if (idx < NN) {
            g_ptr[idx] = run;
            g_cur[idx] = run;
            run += g_cnt[idx];
        }
    }
    if (t == 1023) g_ptr[NN] = run;
}

__global__ void scatter_kernel(const int* __restrict__ ei) {
    int e = blockIdx.x * blockDim.x + threadIdx.x;
    if (e >= ET) return;
    int s, d;
    if (e < EE) { s = ei[e]; d = ei[EE + e]; }
    else        { s = e - EE; d = s; }
    int pos = atomicAdd(&g_cur[d], 1);
    g_csr_src[pos] = s;
}

// ================= fat kernel: gemm0 blocks + hist blocks =================
// gemm0: x[NN,128] @ W0[128,256] -> g_h0h (fp16), fused alpha0
// tile 128x64 (head = blockIdx.x%4), warps 4x2, warp tile 32x32, BK=16
#define SA_S 20
#define SB_S 72
__global__ void gemm0_hist_kernel(const float* __restrict__ A, const float* __restrict__ B,
                                  const float* __restrict__ a_src, const float* __restrict__ a_dst,
                                  const int* __restrict__ ei) {
    if (blockIdx.x >= NBG0) {
        // histogram of dst over the EE real edges
        int tid = (blockIdx.x - NBG0) * blockDim.x + threadIdx.x;
        int stride = HBLK * blockDim.x;
        for (int e = tid; e < EE; e += stride)
            atomicAdd(&g_cnt[ei[EE + e]], 1);
        return;
    }

    __shared__ float sA[128 * SA_S];
    __shared__ float sB[16 * SB_S];
    __shared__ float s_as[128], s_ad[128];
    int tid = threadIdx.x;
    int wid = tid >> 5, lane = tid & 31;
    int gid = lane >> 2, tig = lane & 3;
    int warp_m = wid >> 1, warp_n = wid & 1;
    int head = blockIdx.x % 4;
    int by = blockIdx.x / 4;
    int brow = by * 128, bcol = head * 64;

    float acc[2][4][4];
    #pragma unroll
    for (int mt = 0; mt < 2; mt++)
        #pragma unroll
        for (int nt = 0; nt < 4; nt++)
            #pragma unroll
            for (int q = 0; q < 4; q++) acc[mt][nt][q] = 0.0f;

    for (int k0 = 0; k0 < 128; k0 += 16) {
        #pragma unroll
        for (int i = tid; i < 128 * 4; i += 256) {
            int r = i >> 2, cq = (i & 3) * 4;
            int gr = brow + r;
            float4 v = make_float4(0.f, 0.f, 0.f, 0.f);
            if (gr < NN) v = *(const float4*)(A + gr * 128 + k0 + cq);
            sA[r * SA_S + cq]     = tf32r(v.x);
            sA[r * SA_S + cq + 1] = tf32r(v.y);
            sA[r * SA_S + cq + 2] = tf32r(v.z);
            sA[r * SA_S + cq + 3] = tf32r(v.w);
        }
        #pragma unroll
        for (int i = tid; i < 16 * 16; i += 256) {
            int r = i >> 4, cq = (i & 15) * 4;
            float4 v = *(const float4*)(B + (k0 + r) * C0 + bcol + cq);
            sB[r * SB_S + cq]     = tf32r(v.x);
            sB[r * SB_S + cq + 1] = tf32r(v.y);
            sB[r * SB_S + cq + 2] = tf32r(v.z);
            sB[r * SB_S + cq + 3] = tf32r(v.w);
        }
        __syncthreads();
        #pragma unroll
        for (int ks = 0; ks < 16; ks += 8) {
            unsigned af[2][4];
            #pragma unroll
            for (int mt = 0; mt < 2; mt++) {
                int r0 = (warp_m * 32 + mt * 16 + gid) * SA_S;
                af[mt][0] = __float_as_uint(sA[r0 + ks + tig]);
                af[mt][1] = __float_as_uint(sA[r0 + 8 * SA_S + ks + tig]);
                af[mt][2] = __float_as_uint(sA[r0 + ks + tig + 4]);
                af[mt][3] = __float_as_uint(sA[r0 + 8 * SA_S + ks + tig + 4]);
            }
            unsigned bf[4][2];
            #pragma unroll
            for (int nt = 0; nt < 4; nt++) {
                int col = warp_n * 32 + nt * 8 + gid;
                bf[nt][0] = __float_as_uint(sB[(ks + tig) * SB_S + col]);
                bf[nt][1] = __float_as_uint(sB[(ks + tig + 4) * SB_S + col]);
            }
            #pragma unroll
            for (int mt = 0; mt < 2; mt++)
                #pragma unroll
                for (int nt = 0; nt < 4; nt++)
                    mma_tf32(acc[mt][nt][0], acc[mt][nt][1], acc[mt][nt][2], acc[mt][nt][3],
                             af[mt][0], af[mt][1], af[mt][2], af[mt][3],
                             bf[nt][0], bf[nt][1]);
        }
        __syncthreads();
    }

    if (tid < 128) { s_as[tid] = 0.0f; s_ad[tid] = 0.0f; }
    __syncthreads();

    float asp[2][2] = {}, adp[2][2] = {};
    #pragma unroll
    for (int mt = 0; mt < 2; mt++) {
        int r0 = brow + warp_m * 32 + mt * 16 + gid;
        #pragma unroll
        for (int nt = 0; nt < 4; nt++) {
            int hcol = warp_n * 32 + nt * 8 + tig * 2;
            float av0 = a_src[head * HD + hcol],  av1 = a_src[head * HD + hcol + 1];
            float dv0 = a_dst[head * HD + hcol],  dv1 = a_dst[head * HD + hcol + 1];
            float d0 = acc[mt][nt][0], d1 = acc[mt][nt][1];
            float d2 = acc[mt][nt][2], d3 = acc[mt][nt][3];
            asp[mt][0] += d0 * av0 + d1 * av1;
            asp[mt][1] += d2 * av0 + d3 * av1;
            adp[mt][0] += d0 * dv0 + d1 * dv1;
            adp[mt][1] += d2 * dv0 + d3 * dv1;
            int col = bcol + hcol;
            if (r0 < NN)     *(__half2*)(g_h0h + r0 * C0 + col)       = __floats2half2_rn(d0, d1);
            if (r0 + 8 < NN) *(__half2*)(g_h0h + (r0 + 8) * C0 + col) = __floats2half2_rn(d2, d3);
        }
    }
    #pragma unroll
    for (int off = 1; off <= 2; off <<= 1) {
        #pragma unroll
        for (int mt = 0; mt < 2; mt++) {
            asp[mt][0] += __shfl_xor_sync(0xffffffffu, asp[mt][0], off);
            asp[mt][1] += __shfl_xor_sync(0xffffffffu, asp[mt][1], off);
            adp[mt][0] += __shfl_xor_sync(0xffffffffu, adp[mt][0], off);
            adp[mt][1] += __shfl_xor_sync(0xffffffffu, adp[mt][1], off);
        }
    }
    if (tig == 0) {
        #pragma unroll
        for (int mt = 0; mt < 2; mt++) {
            int lr = warp_m * 32 + mt * 16 + gid;
            atomicAdd(&s_as[lr], asp[mt][0]);
            atomicAdd(&s_as[lr + 8], asp[mt][1]);
            atomicAdd(&s_ad[lr], adp[mt][0]);
            atomicAdd(&s_ad[lr + 8], adp[mt][1]);
        }
    }
    __syncthreads();
    if (tid < 128) {
        int gr = brow + tid;
        if (gr < NN) {
            g_as0[gr * H0 + head] = s_as[tid];
            g_ad0[gr * H0 + head] = s_ad[tid];
        }
    }
}

// ---------------- layer0: CSR softmax (no max-shift) + aggregate + BN + ReLU ----------------
// warp per node; lane covers 8 contiguous cols (fp16 gather, 16B per lane per edge)
__global__ void agg0_csr(const float* __restrict__ b0,
                         const float* __restrict__ bn_g, const float* __restrict__ bn_b,
                         const float* __restrict__ bn_m, const float* __restrict__ bn_v) {
    int n = (blockIdx.x * blockDim.x + threadIdx.x) >> 5;
    if (n >= NN) return;
    int lane = threadIdx.x & 31;
    int hc = lane >> 3;                  // head for this lane's 8 cols
    int beg = g_ptr[n], end = g_ptr[n + 1];
    float ad = g_ad0[n * H0 + hc];

    float den = 0.0f;
    float a0 = 0, a1 = 0, a2 = 0, a3 = 0, a4 = 0, a5 = 0, a6 = 0, a7 = 0;
    for (int i = beg; i < end; i++) {
        int s = g_csr_src[i];
        float e = leaky(g_as0[s * H0 + hc] + ad);
        float w = __expf(e);
        den += w;
        uint4 hv = *(const uint4*)(g_h0h + (size_t)s * C0 + lane * 8);
        const __half2* hp = (const __half2*)&hv;
        float2 f0 = __half22float2(hp[0]);
        float2 f1 = __half22float2(hp[1]);
        float2 f2 = __half22float2(hp[2]);
        float2 f3 = __half22float2(hp[3]);
        a0 += w * f0.x; a1 += w * f0.y;
        a2 += w * f1.x; a3 += w * f1.y;
        a4 += w * f2.x; a5 += w * f2.y;
        a6 += w * f3.x; a7 += w * f3.y;
    }
    float inv = 1.0f / den;

    int c = lane * 8;
    float4 bL = *(const float4*)(b0 + c),   bH = *(const float4*)(b0 + c + 4);
    float4 gL = *(const float4*)(bn_g + c), gH = *(const float4*)(bn_g + c + 4);
    float4 tL = *(const float4*)(bn_b + c), tH = *(const float4*)(bn_b + c + 4);
    float4 mL = *(const float4*)(bn_m + c), mH = *(const float4*)(bn_m + c + 4);
    float4 vL = *(const float4*)(bn_v + c), vH = *(const float4*)(bn_v + c + 4);
    float o0 = fmaxf((a0 * inv + bL.x - mL.x) * (gL.x * rsqrtf(vL.x + 1e-5f)) + tL.x, 0.0f);
    float o1 = fmaxf((a1 * inv + bL.y - mL.y) * (gL.y * rsqrtf(vL.y + 1e-5f)) + tL.y, 0.0f);
    float o2 = fmaxf((a2 * inv + bL.z - mL.z) * (gL.z * rsqrtf(vL.z + 1e-5f)) + tL.z, 0.0f);
    float o3 = fmaxf((a3 * inv + bL.w - mL.w) * (gL.w * rsqrtf(vL.w + 1e-5f)) + tL.w, 0.0f);
    float o4 = fmaxf((a4 * inv + bH.x - mH.x) * (gH.x * rsqrtf(vH.x + 1e-5f)) + tH.x, 0.0f);
    float o5 = fmaxf((a5 * inv + bH.y - mH.y) * (gH.y * rsqrtf(vH.y + 1e-5f)) + tH.y, 0.0f);
    float o6 = fmaxf((a6 * inv + bH.z - mH.z) * (gH.z * rsqrtf(vH.z + 1e-5f)) + tH.z, 0.0f);
    float o7 = fmaxf((a7 * inv + bH.w - mH.w) * (gH.w * rsqrtf(vH.w + 1e-5f)) + tH.w, 0.0f);

    uint4 outv;
    __half2* op = (__half2*)&outv;
    op[0] = __floats2half2_rn(o0, o1);
    op[1] = __floats2half2_rn(o2, o3);
    op[2] = __floats2half2_rn(o4, o5);
    op[3] = __floats2half2_rn(o6, o7);
    *(uint4*)(g_hbh + (size_t)n * C0 + c) = outv;
}

// ================= gemm1: g_hbh[NN,256](fp16) @ W1[256,32] -> g_h1, fused alpha1 =================
#define SB1_S 40
__global__ void gemm1_kernel(const float* __restrict__ B,
                             const float* __restrict__ a_src, const float* __restrict__ a_dst) {
    __shared__ float sA[128 * SA_S];
    __shared__ float sB[16 * SB1_S];
    int tid = threadIdx.x;
    int wid = tid >> 5, lane = tid & 31;
    int gid = lane >> 2, tig = lane & 3;
    int brow = blockIdx.y * 128;

    float acc[4][4];
    #pragma unroll
    for (int nt = 0; nt < 4; nt++)
        #pragma unroll
        for (int q = 0; q < 4; q++) acc[nt][q] = 0.0f;

    for (int k0 = 0; k0 < 256; k0 += 16) {
        #pragma unroll
        for (int i = tid; i < 256; i += 256) {
            int r = i >> 1, c8 = (i & 1) * 8;
            int gr = brow + r;
            uint4 hv = make_uint4(0, 0, 0, 0);
            if (gr < NN) hv = *(const uint4*)(g_hbh + (size_t)gr * C0 + k0 + c8);
            const __half2* hp = (const __half2*)&hv;
            float2 f0 = __half22float2(hp[0]);
            float2 f1 = __half22float2(hp[1]);
            float2 f2 = __half22float2(hp[2]);
            float2 f3 = __half22float2(hp[3]);
            sA[r * SA_S + c8]     = f0.x;
            sA[r * SA_S + c8 + 1] = f0.y;
            sA[r * SA_S + c8 + 2] = f1.x;
            sA[r * SA_S + c8 + 3] = f1.y;
            sA[r * SA_S + c8 + 4] = f2.x;
            sA[r * SA_S + c8 + 5] = f2.y;
            sA[r * SA_S + c8 + 6] = f3.x;
            sA[r * SA_S + c8 + 7] = f3.y;
        }
        if (tid < 128) {
            int r = tid >> 3, cq = (tid & 7) * 4;
            float4 v = *(const float4*)(B + (k0 + r) * C1 + cq);
            sB[r * SB1_S + cq]     = tf32r(v.x);
            sB[r * SB1_S + cq + 1] = tf32r(v.y);
            sB[r * SB1_S + cq + 2] = tf32r(v.z);
            sB[r * SB1_S + cq + 3] = tf32r(v.w);
        }
        __syncthreads();
        #pragma unroll
        for (int ks = 0; ks < 16; ks += 8) {
            int r0 = (wid * 16 + gid) * SA_S;
            unsigned a0 = __float_as_uint(sA[r0 + ks + tig]);
            unsigned a1 = __float_as_uint(sA[r0 + 8 * SA_S + ks + tig]);
            unsigned a2 = __float_as_uint(sA[r0 + ks + tig + 4]);
            unsigned a3 = __float_as_uint(sA[r0 + 8 * SA_S + ks + tig + 4]);
            #pragma unroll
            for (int nt = 0; nt < 4; nt++) {
                int col = nt * 8 + gid;
                unsigned b0 = __float_as_uint(sB[(ks + tig) * SB1_S + col]);
                unsigned b1 = __float_as_uint(sB[(ks + tig + 4) * SB1_S + col]);
                mma_tf32(acc[nt][0], acc[nt][1], acc[nt][2], acc[nt][3],
                         a0, a1, a2, a3, b0, b1);
            }
        }
        __syncthreads();
    }

    int r0 = brow + wid * 16 + gid;
    float as0 = 0, as1 = 0, ad0 = 0, ad1 = 0;
    #pragma unroll
    for (int nt = 0; nt < 4; nt++) {
        int col = nt * 8 + tig * 2;
        float av0 = a_src[col], av1 = a_src[col + 1];
        float dv0 = a_dst[col], dv1 = a_dst[col + 1];
        float d0 = acc[nt][0], d1 = acc[nt][1], d2 = acc[nt][2], d3 = acc[nt][3];
        as0 += d0 * av0 + d1 * av1;
        as1 += d2 * av0 + d3 * av1;
        ad0 += d0 * dv0 + d1 * dv1;
        ad1 += d2 * dv0 + d3 * dv1;
        if (r0 < NN)     *(float2*)(g_h1 + r0 * C1 + col)       = make_float2(d0, d1);
        if (r0 + 8 < NN) *(float2*)(g_h1 + (r0 + 8) * C1 + col) = make_float2(d2, d3);
    }
    #pragma unroll
    for (int off = 1; off <= 2; off <<= 1) {
        as0 += __shfl_xor_sync(0xffffffffu, as0, off);
        as1 += __shfl_xor_sync(0xffffffffu, as1, off);
        ad0 += __shfl_xor_sync(0xffffffffu, ad0, off);
        ad1 += __shfl_xor_sync(0xffffffffu, ad1, off);
    }
    if (tig == 0) {
        if (r0 < NN)     { g_as1[r0] = as0;     g_ad1[r0] = ad0; }
        if (r0 + 8 < NN) { g_as1[r0 + 8] = as1; g_ad1[r0 + 8] = ad1; }
    }
}

// ---------------- layer1: CSR softmax (no max-shift) + aggregate + b1 + colsum ----------------
__global__ void agg1_csr(float* __restrict__ emb, const float* __restrict__ b1) {
    int n = (blockIdx.x * blockDim.x + threadIdx.x) >> 5;
    if (n >= NN) return;
    int lane = threadIdx.x & 31;
    int beg = g_ptr[n], end = g_ptr[n + 1];
    float adn = g_ad1[n];

    float sum = 0.0f, acc = 0.0f;
    for (int i = beg; i < end; i++) {
        int s = g_csr_src[i];
        float wv = __expf(leaky(g_as1[s] + adn));
        sum += wv;
        acc += g_h1[s * C1 + lane] * wv;
    }
    float val = acc / sum + b1[lane];
    emb[n * C1 + lane] = val;
    atomicAdd(&g_gsum[lane], val);
}

// ---------------- prediction head ----------------
__global__ void predict_kernel(const float* __restrict__ hW1, const float* __restrict__ hb1,
                               const float* __restrict__ hW2, const float* __restrict__ hb2,
                               float* __restrict__ out, int pred_idx) {
    __shared__ float ge[C1];
    __shared__ float red[64];
    int t = threadIdx.x;
    if (t < C1) ge[t] = g_gsum[t] * (1.0f / (float)NN);
    __syncthreads();
    float s = hb1[t];
    #pragma unroll
    for (int c = 0; c < C1; c++) s += ge[c] * hW1[c * 64 + t];
    float v = fmaxf(s, 0.0f) * hW2[t];
    red[t] = v;
    __syncthreads();
    #pragma unroll
    for (int off = 32; off > 0; off >>= 1) {
        if (t < off) red[t] += red[t + off];
        __syncthreads();
    }
    if (t == 0) out[pred_idx] = red[0] + hb2[0];
}

// ---------------- launch ----------------
extern "C" void kernel_launch(void* const* d_in, const int* in_sizes, int n_in,
                              void* d_out, int out_size) {
    const float* x       = (const float*)d_in[0];
    const int*   ei      = (const int*)d_in[1];
    const float* W0      = (const float*)d_in[2];
    const float* a_src0  = (const float*)d_in[3];
    const float* a_dst0  = (const float*)d_in[4];
    const float* b0      = (const float*)d_in[5];
    const float* bn_g    = (const float*)d_in[6];
    const float* bn_b    = (const float*)d_in[7];
    const float* bn_m    = (const float*)d_in[8];
    const float* bn_v    = (const float*)d_in[9];
    const float* W1      = (const float*)d_in[10];
    const float* a_src1  = (const float*)d_in[11];
    const float* a_dst1  = (const float*)d_in[12];
    const float* b1      = (const float*)d_in[13];
    const float* hW1     = (const float*)d_in[14];
    const float* hb1     = (const float*)d_in[15];
    const float* hW2     = (const float*)d_in[16];
    const float* hb2     = (const float*)d_in[17];
    float* out = (float*)d_out;

    init_kernel<<<256, 256>>>();
    gemm0_hist_kernel<<<NBG0 + HBLK, 256>>>(x, W0, a_src0, a_dst0, ei);
    scan_kernel<<<1, 1024>>>();
    scatter_kernel<<<(ET + 255) / 256, 256>>>(ei);
    agg0_csr<<<(NN * 32 + 255) / 256, 256>>>(b0, bn_g, bn_b, bn_m, bn_v);
    {
        dim3 grid(1, (NN + 127) / 128);
        gemm1_kernel<<<grid, 256>>>(W1, a_src1, a_dst1);
    }
    agg1_csr<<<(NN * 32 + 255) / 256, 256>>>(out, b1);
    predict_kernel<<<1, 64>>>(hW1, hb1, hW2, hb2, out, out_size - 1);
}

// round 10
// speedup vs baseline: 3.2340x; 1.2374x over previous
#include <cuda_runtime.h>
#include <cuda_bf16.h>
#include <cuda_fp16.h>
#include <math.h>

#define NN 50000
#define EE 800000
#define ET (EE + NN)
#define C0 256
#define H0 4
#define HD 64
#define C1 32
#define NEG 0.2f

#define ROWB 391            // total 128-row blocks for gemm0
#define NA 196              // row blocks in part A
#define NB (ROWB - NA)      // row blocks in part B
#define HBLK 256            // hist blocks (fused in part A launch)
#define SCB 512             // scatter blocks (fused in part B launch)

// ---------------- device scratch (zero-initialized at load) ----------------
__device__ __half g_h0h[NN * C0];
__device__ __half g_hbh[NN * C0];
__device__ float g_as0[NN * H0];
__device__ float g_ad0[NN * H0];
__device__ float g_h1[NN * C1];
__device__ float g_as1[NN];
__device__ float g_ad1[NN];
__device__ float g_gsum[C1];          // zeroed by last agg1 block each run
__device__ int g_cnt[NN];             // zeroed by scan each run
__device__ int g_ptr[NN + 1];
__device__ int g_cur[NN];
__device__ unsigned g_done;           // zeroed by last agg1 block each run
__device__ int g_csr_src[ET];

// ---------------- tf32 helpers ----------------
__device__ __forceinline__ float tf32r(float f) {
    unsigned int u;
    asm("cvt.rna.tf32.f32 %0, %1;" : "=r"(u) : "f"(f));
    return __uint_as_float(u);
}
__device__ __forceinline__ void mma_tf32(float& d0, float& d1, float& d2, float& d3,
                                         unsigned a0, unsigned a1, unsigned a2, unsigned a3,
                                         unsigned b0, unsigned b1) {
    asm volatile("mma.sync.aligned.m16n8k8.row.col.f32.tf32.tf32.f32 "
                 "{%0,%1,%2,%3}, {%4,%5,%6,%7}, {%8,%9}, {%0,%1,%2,%3};"
                 : "+f"(d0), "+f"(d1), "+f"(d2), "+f"(d3)
                 : "r"(a0), "r"(a1), "r"(a2), "r"(a3), "r"(b0), "r"(b1));
}

__device__ __forceinline__ float leaky(float v) { return (v > 0.0f) ? v : NEG * v; }

// ---------------- gemm0 body: 128x64 tile (one head), warps 4x2, BK=16 ----------------
#define SA_S 20
#define SB_S 72
__device__ __forceinline__ void gemm0_body(int by, int head,
                                           const float* __restrict__ A,
                                           const float* __restrict__ B,
                                           const float* __restrict__ a_src,
                                           const float* __restrict__ a_dst) {
    __shared__ float sA[128 * SA_S];
    __shared__ float sB[16 * SB_S];
    __shared__ float s_as[128], s_ad[128];
    int tid = threadIdx.x;
    int wid = tid >> 5, lane = tid & 31;
    int gid = lane >> 2, tig = lane & 3;
    int warp_m = wid >> 1, warp_n = wid & 1;
    int brow = by * 128, bcol = head * 64;

    float acc[2][4][4];
    #pragma unroll
    for (int mt = 0; mt < 2; mt++)
        #pragma unroll
        for (int nt = 0; nt < 4; nt++)
            #pragma unroll
            for (int q = 0; q < 4; q++) acc[mt][nt][q] = 0.0f;

    for (int k0 = 0; k0 < 128; k0 += 16) {
        #pragma unroll
        for (int i = tid; i < 128 * 4; i += 256) {
            int r = i >> 2, cq = (i & 3) * 4;
            int gr = brow + r;
            float4 v = make_float4(0.f, 0.f, 0.f, 0.f);
            if (gr < NN) v = *(const float4*)(A + gr * 128 + k0 + cq);
            sA[r * SA_S + cq]     = tf32r(v.x);
            sA[r * SA_S + cq + 1] = tf32r(v.y);
            sA[r * SA_S + cq + 2] = tf32r(v.z);
            sA[r * SA_S + cq + 3] = tf32r(v.w);
        }
        #pragma unroll
        for (int i = tid; i < 16 * 16; i += 256) {
            int r = i >> 4, cq = (i & 15) * 4;
            float4 v = *(const float4*)(B + (k0 + r) * C0 + bcol + cq);
            sB[r * SB_S + cq]     = tf32r(v.x);
            sB[r * SB_S + cq + 1] = tf32r(v.y);
            sB[r * SB_S + cq + 2] = tf32r(v.z);
            sB[r * SB_S + cq + 3] = tf32r(v.w);
        }
        __syncthreads();
        #pragma unroll
        for (int ks = 0; ks < 16; ks += 8) {
            unsigned af[2][4];
            #pragma unroll
            for (int mt = 0; mt < 2; mt++) {
                int r0 = (warp_m * 32 + mt * 16 + gid) * SA_S;
                af[mt][0] = __float_as_uint(sA[r0 + ks + tig]);
                af[mt][1] = __float_as_uint(sA[r0 + 8 * SA_S + ks + tig]);
                af[mt][2] = __float_as_uint(sA[r0 + ks + tig + 4]);
                af[mt][3] = __float_as_uint(sA[r0 + 8 * SA_S + ks + tig + 4]);
            }
            unsigned bf[4][2];
            #pragma unroll
            for (int nt = 0; nt < 4; nt++) {
                int col = warp_n * 32 + nt * 8 + gid;
                bf[nt][0] = __float_as_uint(sB[(ks + tig) * SB_S + col]);
                bf[nt][1] = __float_as_uint(sB[(ks + tig + 4) * SB_S + col]);
            }
            #pragma unroll
            for (int mt = 0; mt < 2; mt++)
                #pragma unroll
                for (int nt = 0; nt < 4; nt++)
                    mma_tf32(acc[mt][nt][0], acc[mt][nt][1], acc[mt][nt][2], acc[mt][nt][3],
                             af[mt][0], af[mt][1], af[mt][2], af[mt][3],
                             bf[nt][0], bf[nt][1]);
        }
        __syncthreads();
    }

    if (tid < 128) { s_as[tid] = 0.0f; s_ad[tid] = 0.0f; }
    __syncthreads();

    float asp[2][2] = {}, adp[2][2] = {};
    #pragma unroll
    for (int mt = 0; mt < 2; mt++) {
        int r0 = brow + warp_m * 32 + mt * 16 + gid;
        #pragma unroll
        for (int nt = 0; nt < 4; nt++) {
            int hcol = warp_n * 32 + nt * 8 + tig * 2;
            float av0 = a_src[head * HD + hcol],  av1 = a_src[head * HD + hcol + 1];
            float dv0 = a_dst[head * HD + hcol],  dv1 = a_dst[head * HD + hcol + 1];
            float d0 = acc[mt][nt][0], d1 = acc[mt][nt][1];
            float d2 = acc[mt][nt][2], d3 = acc[mt][nt][3];
            asp[mt][0] += d0 * av0 + d1 * av1;
            asp[mt][1] += d2 * av0 + d3 * av1;
            adp[mt][0] += d0 * dv0 + d1 * dv1;
            adp[mt][1] += d2 * dv0 + d3 * dv1;
            int col = bcol + hcol;
            if (r0 < NN)     *(__half2*)(g_h0h + (size_t)r0 * C0 + col)       = __floats2half2_rn(d0, d1);
            if (r0 + 8 < NN) *(__half2*)(g_h0h + (size_t)(r0 + 8) * C0 + col) = __floats2half2_rn(d2, d3);
        }
    }
    #pragma unroll
    for (int off = 1; off <= 2; off <<= 1) {
        #pragma unroll
        for (int mt = 0; mt < 2; mt++) {
            asp[mt][0] += __shfl_xor_sync(0xffffffffu, asp[mt][0], off);
            asp[mt][1] += __shfl_xor_sync(0xffffffffu, asp[mt][1], off);
            adp[mt][0] += __shfl_xor_sync(0xffffffffu, adp[mt][0], off);
            adp[mt][1] += __shfl_xor_sync(0xffffffffu, adp[mt][1], off);
        }
    }
    if (tig == 0) {
        #pragma unroll
        for (int mt = 0; mt < 2; mt++) {
            int lr = warp_m * 32 + mt * 16 + gid;
            atomicAdd(&s_as[lr], asp[mt][0]);
            atomicAdd(&s_as[lr + 8], asp[mt][1]);
            atomicAdd(&s_ad[lr], adp[mt][0]);
            atomicAdd(&s_ad[lr + 8], adp[mt][1]);
        }
    }
    __syncthreads();
    if (tid < 128) {
        int gr = brow + tid;
        if (gr < NN) {
            g_as0[gr * H0 + head] = s_as[tid];
            g_ad0[gr * H0 + head] = s_ad[tid];
        }
    }
}

// ---------------- L1: hist blocks + gemm0 part A ----------------
__global__ void gemm0a_hist_kernel(const float* __restrict__ A, const float* __restrict__ B,
                                   const float* __restrict__ a_src, const float* __restrict__ a_dst,
                                   const int* __restrict__ ei) {
    if (blockIdx.x < HBLK) {
        int tid = blockIdx.x * blockDim.x + threadIdx.x;
        int stride = HBLK * blockDim.x;
        for (int e = tid; e < EE; e += stride)
            atomicAdd(&g_cnt[ei[EE + e]], 1);
        return;
    }
    int g = blockIdx.x - HBLK;
    gemm0_body(g >> 2, g & 3, A, B, a_src, a_dst);
}

// ---------------- L2: scan (1 block, 1024 threads); zeroes g_cnt ----------------
__global__ void scan_kernel() {
    __shared__ int sums[1024];
    int t = threadIdx.x;
    const int CH = (NN + 1023) / 1024;
    int base = t * CH;
    int cnts[CH];
    int local = 0;
    for (int i = 0; i < CH; i++) {
        int idx = base + i;
        int c = 0;
        if (idx < NN) { c = g_cnt[idx] + 1; g_cnt[idx] = 0; }   // +1 self loop; reset for next run
        cnts[i] = c;
        local += c;
    }
    sums[t] = local;
    __syncthreads();
    for (int off = 1; off < 1024; off <<= 1) {
        int v = (t >= off) ? sums[t - off] : 0;
        __syncthreads();
        sums[t] += v;
        __syncthreads();
    }
    int run = sums[t] - local;
    for (int i = 0; i < CH; i++) {
        int idx = base + i;
        if (idx < NN) {
            g_ptr[idx] = run;
            g_cur[idx] = run;
            run += cnts[i];
        }
    }
    if (t == 1023) g_ptr[NN] = run;
}

// ---------------- L3: gemm0 part B + scatter blocks ----------------
__global__ void gemm0b_scatter_kernel(const float* __restrict__ A, const float* __restrict__ B,
                                      const float* __restrict__ a_src, const float* __restrict__ a_dst,
                                      const int* __restrict__ ei) {
    if (blockIdx.x < NB * 4) {
        int g = blockIdx.x;
        gemm0_body(NA + (g >> 2), g & 3, A, B, a_src, a_dst);
        return;
    }
    int tid = (blockIdx.x - NB * 4) * blockDim.x + threadIdx.x;
    int stride = SCB * blockDim.x;
    for (int e = tid; e < ET; e += stride) {
        int s, d;
        if (e < EE) { s = ei[e]; d = ei[EE + e]; }
        else        { s = e - EE; d = s; }
        int pos = atomicAdd(&g_cur[d], 1);
        g_csr_src[pos] = s;
    }
}

// ---------------- L4: agg0 (CSR softmax no-max + aggregate + BN + ReLU) ----------------
__global__ void agg0_csr(const float* __restrict__ b0,
                         const float* __restrict__ bn_g, const float* __restrict__ bn_b,
                         const float* __restrict__ bn_m, const float* __restrict__ bn_v) {
    int n = (blockIdx.x * blockDim.x + threadIdx.x) >> 5;
    if (n >= NN) return;
    int lane = threadIdx.x & 31;
    int hc = lane >> 3;
    int beg = g_ptr[n], end = g_ptr[n + 1];
    float ad = g_ad0[n * H0 + hc];

    float den = 0.0f;
    float a0 = 0, a1 = 0, a2 = 0, a3 = 0, a4 = 0, a5 = 0, a6 = 0, a7 = 0;
    for (int i = beg; i < end; i++) {
        int s = g_csr_src[i];
        float e = leaky(g_as0[s * H0 + hc] + ad);
        float w = __expf(e);
        den += w;
        uint4 hv = *(const uint4*)(g_h0h + (size_t)s * C0 + lane * 8);
        const __half2* hp = (const __half2*)&hv;
        float2 f0 = __half22float2(hp[0]);
        float2 f1 = __half22float2(hp[1]);
        float2 f2 = __half22float2(hp[2]);
        float2 f3 = __half22float2(hp[3]);
        a0 += w * f0.x; a1 += w * f0.y;
        a2 += w * f1.x; a3 += w * f1.y;
        a4 += w * f2.x; a5 += w * f2.y;
        a6 += w * f3.x; a7 += w * f3.y;
    }
    float inv = 1.0f / den;

    int c = lane * 8;
    float4 bL = *(const float4*)(b0 + c),   bH = *(const float4*)(b0 + c + 4);
    float4 gL = *(const float4*)(bn_g + c), gH = *(const float4*)(bn_g + c + 4);
    float4 tL = *(const float4*)(bn_b + c), tH = *(const float4*)(bn_b + c + 4);
    float4 mL = *(const float4*)(bn_m + c), mH = *(const float4*)(bn_m + c + 4);
    float4 vL = *(const float4*)(bn_v + c), vH = *(const float4*)(bn_v + c + 4);
    float o0 = fmaxf((a0 * inv + bL.x - mL.x) * (gL.x * rsqrtf(vL.x + 1e-5f)) + tL.x, 0.0f);
    float o1 = fmaxf((a1 * inv + bL.y - mL.y) * (gL.y * rsqrtf(vL.y + 1e-5f)) + tL.y, 0.0f);
    float o2 = fmaxf((a2 * inv + bL.z - mL.z) * (gL.z * rsqrtf(vL.z + 1e-5f)) + tL.z, 0.0f);
    float o3 = fmaxf((a3 * inv + bL.w - mL.w) * (gL.w * rsqrtf(vL.w + 1e-5f)) + tL.w, 0.0f);
    float o4 = fmaxf((a4 * inv + bH.x - mH.x) * (gH.x * rsqrtf(vH.x + 1e-5f)) + tH.x, 0.0f);
    float o5 = fmaxf((a5 * inv + bH.y - mH.y) * (gH.y * rsqrtf(vH.y + 1e-5f)) + tH.y, 0.0f);
    float o6 = fmaxf((a6 * inv + bH.z - mH.z) * (gH.z * rsqrtf(vH.z + 1e-5f)) + tH.z, 0.0f);
    float o7 = fmaxf((a7 * inv + bH.w - mH.w) * (gH.w * rsqrtf(vH.w + 1e-5f)) + tH.w, 0.0f);

    uint4 outv;
    __half2* op = (__half2*)&outv;
    op[0] = __floats2half2_rn(o0, o1);
    op[1] = __floats2half2_rn(o2, o3);
    op[2] = __floats2half2_rn(o4, o5);
    op[3] = __floats2half2_rn(o6, o7);
    *(uint4*)(g_hbh + (size_t)n * C0 + c) = outv;
}

// ---------------- L5: gemm1 (fp16 A, tf32 mma) + fused alpha1 ----------------
#define SB1_S 40
__global__ void gemm1_kernel(const float* __restrict__ B,
                             const float* __restrict__ a_src, const float* __restrict__ a_dst) {
    __shared__ float sA[128 * SA_S];
    __shared__ float sB[16 * SB1_S];
    int tid = threadIdx.x;
    int wid = tid >> 5, lane = tid & 31;
    int gid = lane >> 2, tig = lane & 3;
    int brow = blockIdx.y * 128;

    float acc[4][4];
    #pragma unroll
    for (int nt = 0; nt < 4; nt++)
        #pragma unroll
        for (int q = 0; q < 4; q++) acc[nt][q] = 0.0f;

    for (int k0 = 0; k0 < 256; k0 += 16) {
        {
            int i = tid;
            int r = i >> 1, c8 = (i & 1) * 8;
            int gr = brow + r;
            uint4 hv = make_uint4(0, 0, 0, 0);
            if (gr < NN) hv = *(const uint4*)(g_hbh + (size_t)gr * C0 + k0 + c8);
            const __half2* hp = (const __half2*)&hv;
            float2 f0 = __half22float2(hp[0]);
            float2 f1 = __half22float2(hp[1]);
            float2 f2 = __half22float2(hp[2]);
            float2 f3 = __half22float2(hp[3]);
            sA[r * SA_S + c8]     = f0.x;
            sA[r * SA_S + c8 + 1] = f0.y;
            sA[r * SA_S + c8 + 2] = f1.x;
            sA[r * SA_S + c8 + 3] = f1.y;
            sA[r * SA_S + c8 + 4] = f2.x;
            sA[r * SA_S + c8 + 5] = f2.y;
            sA[r * SA_S + c8 + 6] = f3.x;
            sA[r * SA_S + c8 + 7] = f3.y;
        }
        if (tid < 128) {
            int r = tid >> 3, cq = (tid & 7) * 4;
            float4 v = *(const float4*)(B + (k0 + r) * C1 + cq);
            sB[r * SB1_S + cq]     = tf32r(v.x);
            sB[r * SB1_S + cq + 1] = tf32r(v.y);
            sB[r * SB1_S + cq + 2] = tf32r(v.z);
            sB[r * SB1_S + cq + 3] = tf32r(v.w);
        }
        __syncthreads();
        #pragma unroll
        for (int ks = 0; ks < 16; ks += 8) {
            int r0 = (wid * 16 + gid) * SA_S;
            unsigned a0 = __float_as_uint(sA[r0 + ks + tig]);
            unsigned a1 = __float_as_uint(sA[r0 + 8 * SA_S + ks + tig]);
            unsigned a2 = __float_as_uint(sA[r0 + ks + tig + 4]);
            unsigned a3 = __float_as_uint(sA[r0 + 8 * SA_S + ks + tig + 4]);
            #pragma unroll
            for (int nt = 0; nt < 4; nt++) {
                int col = nt * 8 + gid;
                unsigned b0 = __float_as_uint(sB[(ks + tig) * SB1_S + col]);
                unsigned b1 = __float_as_uint(sB[(ks + tig + 4) * SB1_S + col]);
                mma_tf32(acc[nt][0], acc[nt][1], acc[nt][2], acc[nt][3],
                         a0, a1, a2, a3, b0, b1);
            }
        }
        __syncthreads();
    }

    int r0 = brow + wid * 16 + gid;
    float as0 = 0, as1 = 0, ad0 = 0, ad1 = 0;
    #pragma unroll
    for (int nt = 0; nt < 4; nt++) {
        int col = nt * 8 + tig * 2;
        float av0 = a_src[col], av1 = a_src[col + 1];
        float dv0 = a_dst[col], dv1 = a_dst[col + 1];
        float d0 = acc[nt][0], d1 = acc[nt][1], d2 = acc[nt][2], d3 = acc[nt][3];
        as0 += d0 * av0 + d1 * av1;
        as1 += d2 * av0 + d3 * av1;
        ad0 += d0 * dv0 + d1 * dv1;
        ad1 += d2 * dv0 + d3 * dv1;
        if (r0 < NN)     *(float2*)(g_h1 + r0 * C1 + col)       = make_float2(d0, d1);
        if (r0 + 8 < NN) *(float2*)(g_h1 + (r0 + 8) * C1 + col) = make_float2(d2, d3);
    }
    #pragma unroll
    for (int off = 1; off <= 2; off <<= 1) {
        as0 += __shfl_xor_sync(0xffffffffu, as0, off);
        as1 += __shfl_xor_sync(0xffffffffu, as1, off);
        ad0 += __shfl_xor_sync(0xffffffffu, ad0, off);
        ad1 += __shfl_xor_sync(0xffffffffu, ad1, off);
    }
    if (tig == 0) {
        if (r0 < NN)     { g_as1[r0] = as0;     g_ad1[r0] = ad0; }
        if (r0 + 8 < NN) { g_as1[r0 + 8] = as1; g_ad1[r0 + 8] = ad1; }
    }
}

// ---------------- L6: agg1 + b1 + block-reduced colsum + fused predict (last block) ----------------
__global__ void agg1_pred(float* __restrict__ emb, const float* __restrict__ b1,
                          const float* __restrict__ hW1, const float* __restrict__ hb1,
                          const float* __restrict__ hW2, const float* __restrict__ hb2,
                          float* __restrict__ out, int pred_idx) {
    __shared__ float sred[256];
    __shared__ unsigned s_ticket;
    int tid = threadIdx.x;
    int n = (blockIdx.x * blockDim.x + tid) >> 5;     // grid sized so all n < NN
    int lane = tid & 31;
    int beg = g_ptr[n], end = g_ptr[n + 1];
    float adn = g_ad1[n];

    float sum = 0.0f, acc = 0.0f;
    for (int i = beg; i < end; i++) {
        int s = g_csr_src[i];
        float wv = __expf(leaky(g_as1[s] + adn));
        sum += wv;
        acc += g_h1[s * C1 + lane] * wv;
    }
    float val = acc / sum + b1[lane];
    emb[n * C1 + lane] = val;

    // block reduce for graph-embedding column sums
    sred[tid] = val;
    __syncthreads();
    if (tid < 32) {
        float t = sred[tid];
        #pragma unroll
        for (int r = 1; r < 8; r++) t += sred[r * 32 + tid];
        atomicAdd(&g_gsum[tid], t);
    }
    __threadfence();
    if (tid == 0) s_ticket = atomicAdd(&g_done, 1u);
    __syncthreads();
    if (s_ticket != gridDim.x - 1) return;

    // last block: prediction head
    __shared__ float ge[C1];
    __shared__ float red[64];
    if (tid < C1) ge[tid] = g_gsum[tid] * (1.0f / (float)NN);
    __syncthreads();
    if (tid < 64) {
        float s = hb1[tid];
        #pragma unroll
        for (int c = 0; c < C1; c++) s += ge[c] * hW1[c * 64 + tid];
        red[tid] = fmaxf(s, 0.0f) * hW2[tid];
    }
    __syncthreads();
    if (tid == 0) {
        float t = 0.0f;
        #pragma unroll
        for (int i = 0; i < 64; i++) t += red[i];
        out[pred_idx] = t + hb2[0];
        g_done = 0;                       // reset for next graph replay
    }
    if (tid < C1) g_gsum[tid] = 0.0f;     // reset for next graph replay
}

// ---------------- launch ----------------
extern "C" void kernel_launch(void* const* d_in, const int* in_sizes, int n_in,
                              void* d_out, int out_size) {
    const float* x       = (const float*)d_in[0];
    const int*   ei      = (const int*)d_in[1];
    const float* W0      = (const float*)d_in[2];
    const float* a_src0  = (const float*)d_in[3];
    const float* a_dst0  = (const float*)d_in[4];
    const float* b0      = (const float*)d_in[5];
    const float* bn_g    = (const float*)d_in[6];
    const float* bn_b    = (const float*)d_in[7];
    const float* bn_m    = (const float*)d_in[8];
    const float* bn_v    = (const float*)d_in[9];
    const float* W1      = (const float*)d_in[10];
    const float* a_src1  = (const float*)d_in[11];
    const float* a_dst1  = (const float*)d_in[12];
    const float* b1      = (const float*)d_in[13];
    const float* hW1     = (const float*)d_in[14];
    const float* hb1     = (const float*)d_in[15];
    const float* hW2     = (const float*)d_in[16];
    const float* hb2     = (const float*)d_in[17];
    float* out = (float*)d_out;

    gemm0a_hist_kernel<<<HBLK + NA * 4, 256>>>(x, W0, a_src0, a_dst0, ei);
    scan_kernel<<<1, 1024>>>();
    gemm0b_scatter_kernel<<<NB * 4 + SCB, 256>>>(x, W0, a_src0, a_dst0, ei);
    agg0_csr<<<(NN * 32 + 255) / 256, 256>>>(b0, bn_g, bn_b, bn_m, bn_v);
    {
        dim3 grid(1, (NN + 127) / 128);
        gemm1_kernel<<<grid, 256>>>(W1, a_src1, a_dst1);
    }
    agg1_pred<<<(NN + 7) / 8, 256>>>(out, b1, hW1, hb1, hW2, hb2, out, out_size - 1);
}